// round 1
// baseline (speedup 1.0000x reference)
#include <cuda_runtime.h>
#include <math.h>
#include <stdint.h>

#define B_   8
#define T_   1024
#define D_   768
#define H_   12
#define HD_  64
#define WIN_ 768
#define M_   (B_*T_)   // 8192

// ---------------- scratch (static device globals; no runtime allocation) ---
__device__ float g_x1[M_ * D_];            // ln1 out / ln2 out (reused)
__device__ float g_qkv[M_ * 3 * D_];       // qkv
__device__ float g_attn[M_ * D_];          // attention out (B,T,D layout)
__device__ float g_x2[M_ * D_];            // residual after attn
__device__ float g_h[M_ * 4 * D_];         // mlp hidden

// ---------------- block reduction (256 threads) -----------------------------
__device__ __forceinline__ float block_sum256(float v) {
    __shared__ float sh[8];
    int lane = threadIdx.x & 31, w = threadIdx.x >> 5;
    #pragma unroll
    for (int o = 16; o > 0; o >>= 1) v += __shfl_down_sync(0xffffffffu, v, o);
    if (lane == 0) sh[w] = v;
    __syncthreads();
    float r = 0.f;
    #pragma unroll
    for (int i = 0; i < 8; i++) r += sh[i];
    __syncthreads();
    return r;
}

// ---------------- LayerNorm: one CTA (256 thr) per row of 768 ---------------
__global__ void ln_kernel(const float* __restrict__ x, const float* __restrict__ w,
                          const float* __restrict__ bb, float* __restrict__ y) {
    int row = blockIdx.x;
    const float* xr = x + (size_t)row * D_;
    int t = threadIdx.x;
    float v0 = xr[t], v1 = xr[t + 256], v2 = xr[t + 512];
    float s = block_sum256(v0 + v1 + v2);
    float mu = s * (1.f / 768.f);
    float d0 = v0 - mu, d1 = v1 - mu, d2 = v2 - mu;
    float vs = block_sum256(d0 * d0 + d1 * d1 + d2 * d2);
    float rstd = rsqrtf(vs * (1.f / 768.f) + 1e-5f);
    float* yr = y + (size_t)row * D_;
    yr[t]       = d0 * rstd * w[t]       + bb[t];
    yr[t + 256] = d1 * rstd * w[t + 256] + bb[t + 256];
    yr[t + 512] = d2 * rstd * w[t + 512] + bb[t + 512];
}

// ---------------- SGEMM: C = A[M,K] @ B[K,N] + bias (+resid / gelu) ---------
// 128x128 tile, BK=16, 256 threads, 8x8 per thread.
enum { EPI_BIAS = 0, EPI_BIAS_RES = 1, EPI_BIAS_GELU = 2 };

template <int EPI>
__global__ void __launch_bounds__(256) sgemm_kernel(
    const float* __restrict__ A, const float* __restrict__ Bm,
    const float* __restrict__ bias, const float* __restrict__ R,
    float* __restrict__ C, int M, int N, int K)
{
    __shared__ float As[16][132];   // transposed A tile: As[k][m]
    __shared__ float Bs[16][128];   // Bs[k][n]
    const int tid = threadIdx.x;
    const int bm = blockIdx.y << 7, bn = blockIdx.x << 7;
    const int tm = (tid >> 4) << 3, tn = (tid & 15) << 3;
    const int a_r = tid >> 2,  a_c = (tid & 3) << 2;
    const int b_r = tid >> 5,  b_c = (tid & 31) << 2;

    float acc[8][8];
    #pragma unroll
    for (int i = 0; i < 8; i++)
        #pragma unroll
        for (int j = 0; j < 8; j++) acc[i][j] = 0.f;

    for (int k0 = 0; k0 < K; k0 += 16) {
        #pragma unroll
        for (int l = 0; l < 2; l++) {
            int r = a_r + (l << 6);
            float4 va = *(const float4*)(A + (size_t)(bm + r) * K + (k0 + a_c));
            As[a_c + 0][r] = va.x; As[a_c + 1][r] = va.y;
            As[a_c + 2][r] = va.z; As[a_c + 3][r] = va.w;
        }
        #pragma unroll
        for (int l = 0; l < 2; l++) {
            int r = b_r + (l << 3);
            *(float4*)(&Bs[r][b_c]) = *(const float4*)(Bm + (size_t)(k0 + r) * N + (bn + b_c));
        }
        __syncthreads();
        #pragma unroll
        for (int kk = 0; kk < 16; kk++) {
            float4 a0 = *(const float4*)(&As[kk][tm]);
            float4 a1 = *(const float4*)(&As[kk][tm + 4]);
            float4 b0 = *(const float4*)(&Bs[kk][tn]);
            float4 b1 = *(const float4*)(&Bs[kk][tn + 4]);
            float av[8] = {a0.x, a0.y, a0.z, a0.w, a1.x, a1.y, a1.z, a1.w};
            float bv[8] = {b0.x, b0.y, b0.z, b0.w, b1.x, b1.y, b1.z, b1.w};
            #pragma unroll
            for (int i = 0; i < 8; i++)
                #pragma unroll
                for (int j = 0; j < 8; j++)
                    acc[i][j] = fmaf(av[i], bv[j], acc[i][j]);
        }
        __syncthreads();
    }

    #pragma unroll
    for (int i = 0; i < 8; i++) {
        size_t row = (size_t)(bm + tm + i);
        #pragma unroll
        for (int jb = 0; jb < 2; jb++) {
            int col = bn + tn + jb * 4;
            float ov[4];
            #pragma unroll
            for (int jj = 0; jj < 4; jj++) {
                float val = acc[i][jb * 4 + jj] + bias[col + jj];
                if (EPI == EPI_BIAS_RES)  val += R[row * N + col + jj];
                if (EPI == EPI_BIAS_GELU) val = 0.5f * val * (1.f + erff(val * 0.7071067811865476f));
                ov[jj] = val;
            }
            float4 o4 = {ov[0], ov[1], ov[2], ov[3]};
            *(float4*)(C + row * N + col) = o4;
        }
    }
}

// ---------------- Attention: flash-style, windowed causal -------------------
// grid (T/64, H, B), 256 threads. 64-query x 64-key tiles, HD=64.
// Smem: Qt[d][q], Kt[d][k] (token-minor, float4 over tokens), Vs[k][d], St[k][q].
#define PAD68 68
#define ATTN_SMEM_BYTES ((4 * 64 * PAD68 + 3 * 64 + 64) * 4)

__global__ void __launch_bounds__(256) attn_kernel(
    const float* __restrict__ qkv, const int* __restrict__ amask,
    float* __restrict__ out)
{
    extern __shared__ float sm[];
    float* Qt   = sm;                    // [64][68]  Qt[d*68 + q]
    float* Kt   = Qt + 64 * PAD68;       // [64][68]  Kt[d*68 + k]
    float* Vs   = Kt + 64 * PAD68;       // [64][68]  Vs[k*68 + d]
    float* St   = Vs + 64 * PAD68;       // [64][68]  St[k*68 + q]
    float* m_s  = St + 64 * PAD68;       // [64]
    float* l_s  = m_s + 64;              // [64]
    float* al_s = l_s + 64;              // [64]
    int*   kmsk = (int*)(al_s + 64);     // [64]

    const int qi = blockIdx.x, h = blockIdx.y, b = blockIdx.z;
    const int qb = qi * 64;
    const int tid = threadIdx.x;
    const float scale = 0.125f;   // 1/sqrt(64)

    // load Q tile transposed
    {
        int d = tid & 63, r0 = tid >> 6;
        const float* qp = qkv + ((size_t)(b * T_ + qb)) * (3 * D_) + h * 64 + d;
        #pragma unroll
        for (int r = r0; r < 64; r += 4)
            Qt[d * PAD68 + r] = qp[(size_t)r * (3 * D_)];
    }
    if (tid < 64) { m_s[tid] = -1e30f; l_s[tid] = 0.f; }

    const int ty = tid >> 4, tx = tid & 15;
    const int q0 = ty * 4, k0 = tx * 4;
    float o[4][4];
    #pragma unroll
    for (int i = 0; i < 4; i++)
        #pragma unroll
        for (int j = 0; j < 4; j++) o[i][j] = 0.f;

    int jlo = qb - (WIN_ - 1);
    int kt0 = (jlo > 0 ? jlo : 0) >> 6;

    for (int kt = kt0; kt <= qi; kt++) {
        const int kb = kt * 64;
        __syncthreads();   // protect Q load (iter 1) / previous O-update reads
        {
            int d = tid & 63, r0 = tid >> 6;
            const float* kp = qkv + ((size_t)(b * T_ + kb)) * (3 * D_) + D_ + h * 64;
            const float* vp = kp + D_;
            #pragma unroll
            for (int r = r0; r < 64; r += 4) {
                Kt[d * PAD68 + r] = kp[(size_t)r * (3 * D_) + d];
                Vs[r * PAD68 + d] = vp[(size_t)r * (3 * D_) + d];
            }
            if (tid < 64) kmsk[tid] = amask[b * T_ + kb + tid];
        }
        __syncthreads();

        // S = scale * Q K^T  (each thread 4q x 4k)
        float acc[4][4];
        #pragma unroll
        for (int i = 0; i < 4; i++)
            #pragma unroll
            for (int j = 0; j < 4; j++) acc[i][j] = 0.f;
        #pragma unroll 8
        for (int d = 0; d < 64; d++) {
            float4 qv = *(const float4*)(&Qt[d * PAD68 + q0]);
            float4 kv = *(const float4*)(&Kt[d * PAD68 + k0]);
            float qa[4] = {qv.x, qv.y, qv.z, qv.w};
            float ka[4] = {kv.x, kv.y, kv.z, kv.w};
            #pragma unroll
            for (int i = 0; i < 4; i++)
                #pragma unroll
                for (int j = 0; j < 4; j++)
                    acc[i][j] = fmaf(qa[i], ka[j], acc[i][j]);
        }
        #pragma unroll
        for (int jj = 0; jj < 4; jj++) {
            int j = kb + k0 + jj;
            int km = kmsk[k0 + jj];
            #pragma unroll
            for (int ii = 0; ii < 4; ii++) {
                int i = qb + q0 + ii;
                bool valid = (j <= i) && (j > i - WIN_) && (km != 0);
                St[(k0 + jj) * PAD68 + q0 + ii] = valid ? acc[ii][jj] * scale : -1e30f;
            }
        }
        __syncthreads();

        // online softmax (one thread per query row)
        if (tid < 64) {
            int q = tid;
            float m_old = m_s[q];
            float mt = m_old;
            for (int k = 0; k < 64; k++) mt = fmaxf(mt, St[k * PAD68 + q]);
            float alpha = __expf(m_old - mt);
            float lsum = 0.f;
            for (int k = 0; k < 64; k++) {
                float s = St[k * PAD68 + q];
                float p = (s <= -1e29f) ? 0.f : __expf(s - mt);
                St[k * PAD68 + q] = p;
                lsum += p;
            }
            m_s[q] = mt;
            l_s[q] = l_s[q] * alpha + lsum;
            al_s[q] = alpha;
        }
        __syncthreads();

        // O = alpha*O + P @ V  (each thread 4q x 4d, d0 = tx*4)
        float alv[4];
        #pragma unroll
        for (int ii = 0; ii < 4; ii++) alv[ii] = al_s[q0 + ii];
        #pragma unroll
        for (int ii = 0; ii < 4; ii++)
            #pragma unroll
            for (int jj = 0; jj < 4; jj++) o[ii][jj] *= alv[ii];
        #pragma unroll 8
        for (int k = 0; k < 64; k++) {
            float4 pv = *(const float4*)(&St[k * PAD68 + q0]);
            float4 vv = *(const float4*)(&Vs[k * PAD68 + k0]);  // k0 == tx*4 == d0
            float pa[4] = {pv.x, pv.y, pv.z, pv.w};
            float va[4] = {vv.x, vv.y, vv.z, vv.w};
            #pragma unroll
            for (int ii = 0; ii < 4; ii++)
                #pragma unroll
                for (int jj = 0; jj < 4; jj++)
                    o[ii][jj] = fmaf(pa[ii], va[jj], o[ii][jj]);
        }
    }

    __syncthreads();
    float linv[4];
    #pragma unroll
    for (int ii = 0; ii < 4; ii++) linv[ii] = 1.f / l_s[q0 + ii];
    #pragma unroll
    for (int ii = 0; ii < 4; ii++) {
        float4 r4 = {o[ii][0] * linv[ii], o[ii][1] * linv[ii],
                     o[ii][2] * linv[ii], o[ii][3] * linv[ii]};
        *(float4*)(out + ((size_t)(b * T_ + qb + q0 + ii)) * D_ + h * 64 + tx * 4) = r4;
    }
}

// ---------------- launch -----------------------------------------------------
extern "C" void kernel_launch(void* const* d_in, const int* in_sizes, int n_in,
                              void* d_out, int out_size)
{
    const float* x      = (const float*)d_in[0];
    const int*   amask  = (const int*)d_in[1];
    const float* ln1_w  = (const float*)d_in[2];
    const float* ln1_b  = (const float*)d_in[3];
    const float* w_attn = (const float*)d_in[4];
    const float* b_attn = (const float*)d_in[5];
    const float* w_proj = (const float*)d_in[6];
    const float* b_proj = (const float*)d_in[7];
    const float* ln2_w  = (const float*)d_in[8];
    const float* ln2_b  = (const float*)d_in[9];
    const float* w_fc   = (const float*)d_in[10];
    const float* b_fc   = (const float*)d_in[11];
    const float* w_fcp  = (const float*)d_in[12];
    const float* b_fcp  = (const float*)d_in[13];
    float* out = (float*)d_out;

    float *p_x1, *p_qkv, *p_attn, *p_x2, *p_h;
    cudaGetSymbolAddress((void**)&p_x1,   g_x1);
    cudaGetSymbolAddress((void**)&p_qkv,  g_qkv);
    cudaGetSymbolAddress((void**)&p_attn, g_attn);
    cudaGetSymbolAddress((void**)&p_x2,   g_x2);
    cudaGetSymbolAddress((void**)&p_h,    g_h);

    cudaFuncSetAttribute(attn_kernel, cudaFuncAttributeMaxDynamicSharedMemorySize,
                         ATTN_SMEM_BYTES);

    // 1) ln1
    ln_kernel<<<M_, 256>>>(x, ln1_w, ln1_b, p_x1);
    // 2) qkv = x1 @ w_attn + b_attn       [8192 x 2304 x 768]
    sgemm_kernel<EPI_BIAS><<<dim3(2304 / 128, M_ / 128), 256>>>(
        p_x1, w_attn, b_attn, nullptr, p_qkv, M_, 2304, 768);
    // 3) attention
    attn_kernel<<<dim3(T_ / 64, H_, B_), 256, ATTN_SMEM_BYTES>>>(p_qkv, amask, p_attn);
    // 4) x2 = attn @ w_proj + b_proj + x  [8192 x 768 x 768]
    sgemm_kernel<EPI_BIAS_RES><<<dim3(768 / 128, M_ / 128), 256>>>(
        p_attn, w_proj, b_proj, x, p_x2, M_, 768, 768);
    // 5) ln2
    ln_kernel<<<M_, 256>>>(p_x2, ln2_w, ln2_b, p_x1);
    // 6) h = gelu(x3 @ w_fc + b_fc)       [8192 x 3072 x 768]
    sgemm_kernel<EPI_BIAS_GELU><<<dim3(3072 / 128, M_ / 128), 256>>>(
        p_x1, w_fc, b_fc, nullptr, p_h, M_, 3072, 768);
    // 7) out = h @ w_fc_proj + b_fc_proj + x2   [8192 x 768 x 3072]
    sgemm_kernel<EPI_BIAS_RES><<<dim3(768 / 128, M_ / 128), 256>>>(
        p_h, w_fcp, b_fcp, p_x2, out, M_, 768, 3072);
}

// round 3
// speedup vs baseline: 2.1846x; 2.1846x over previous
#include <cuda_runtime.h>
#include <math.h>
#include <stdint.h>

#define B_   8
#define T_   1024
#define D_   768
#define H_   12
#define WIN_ 768
#define M_   (B_*T_)   // 8192

// ---------------- scratch (static device globals) ---------------------------
__device__ float g_x1[M_ * D_];
__device__ float g_qkv[M_ * 3 * D_];
__device__ float g_attn[M_ * D_];
__device__ float g_x2[M_ * D_];
__device__ float g_h[M_ * 4 * D_];
__device__ float g_w_attn[D_ * 3 * D_];   // tf32-rounded weights (orig layout)
__device__ float g_w_proj[D_ * D_];
__device__ float g_w_fc[D_ * 4 * D_];
__device__ float g_w_fcp[4 * D_ * D_];

// ---------------- helpers -----------------------------------------------------
__device__ __forceinline__ uint32_t smem_to_u32(const void* p) {
    uint32_t a;
    asm("{ .reg .u64 t; cvta.to.shared.u64 t, %1; cvt.u32.u64 %0, t; }" : "=r"(a) : "l"(p));
    return a;
}
__device__ __forceinline__ float round_tf32(float v) {
    uint32_t o;
    asm("cvt.rna.tf32.f32 %0, %1;" : "=r"(o) : "f"(v));
    return __uint_as_float(o);
}
#define CP16(saddr, gptr) \
    asm volatile("cp.async.cg.shared.global [%0], [%1], 16;" :: "r"(saddr), "l"(gptr))
#define CP_COMMIT() asm volatile("cp.async.commit_group;" ::: "memory")
#define CP_WAIT2()  asm volatile("cp.async.wait_group 2;" ::: "memory")

__device__ __forceinline__ void mma1688(float* d, const uint32_t* a, const uint32_t* b) {
    asm volatile(
        "mma.sync.aligned.m16n8k8.row.col.f32.tf32.tf32.f32 "
        "{%0,%1,%2,%3}, {%4,%5,%6,%7}, {%8,%9}, {%0,%1,%2,%3};"
        : "+f"(d[0]), "+f"(d[1]), "+f"(d[2]), "+f"(d[3])
        : "r"(a[0]), "r"(a[1]), "r"(a[2]), "r"(a[3]), "r"(b[0]), "r"(b[1]));
}

// ---------------- tf32 tensor-core GEMM ---------------------------------------
// C[M,N] = A[M,K] @ W[K,N] + bias (+res / gelu). A fp32 (tf32-rounded by
// producer), W pre-rounded. 128x128 tile, BK=16, 8 warps (64x32 each),
// 3-stage cp.async pipeline.
enum { EPI_BIAS = 0, EPI_BIAS_RES = 1, EPI_BIAS_GELU = 2 };

#define APAD 20          // As row stride (floats)
#define BPAD 136         // Bs row stride (floats)
#define STG_F (128 * APAD + 16 * BPAD)   // floats per stage = 4736
#define GEMM_SMEM (3 * STG_F * 4)        // 56832 B

template <int EPI>
__global__ void __launch_bounds__(256, 2) mma_gemm(
    const float* __restrict__ A, const float* __restrict__ W,
    const float* __restrict__ bias, const float* __restrict__ R,
    float* __restrict__ C, int N, int K)
{
    extern __shared__ float sm[];
    const int tid = threadIdx.x;
    const int wid = tid >> 5, lane = tid & 31;
    const int wm = wid >> 2, wn = wid & 3;           // 2 x 4 warp grid
    const int bm = blockIdx.y << 7, bn = blockIdx.x << 7;
    const int lr = lane >> 2, lc = lane & 3;
    const int NIT = K >> 4;

    // per-thread load coordinates
    const int am = tid >> 1, ac = tid & 1;           // A: row, chunk base
    const int br = tid >> 4, bc = tid & 15;          // B: row, chunk base
    const float* gA = A + (size_t)(bm + am) * K;
    const float* gB = W + (size_t)br * N + bn;

    float acc[4][4][4];
    #pragma unroll
    for (int i = 0; i < 4; i++)
        #pragma unroll
        for (int j = 0; j < 4; j++)
            #pragma unroll
            for (int k = 0; k < 4; k++) acc[i][j][k] = 0.f;

    auto load_stage = [&](int s, int kt) {
        float* As_ = sm + s * STG_F;
        float* Bs_ = As_ + 128 * APAD;
        uint32_t sa = smem_to_u32(As_ + am * APAD);
        const float* ga = gA + (kt << 4);
        CP16(sa + (ac * 4) * 4,       ga + ac * 4);
        CP16(sa + ((ac + 2) * 4) * 4, ga + (ac + 2) * 4);
        uint32_t sb = smem_to_u32(Bs_ + br * BPAD);
        const float* gb = gB + (size_t)(kt << 4) * N;
        CP16(sb + (bc * 4) * 4,        gb + bc * 4);
        CP16(sb + ((bc + 16) * 4) * 4, gb + (bc + 16) * 4);
    };

    load_stage(0, 0); CP_COMMIT();
    load_stage(1, 1); CP_COMMIT();

    for (int it = 0; it < NIT; it++) {
        if (it + 2 < NIT) load_stage((it + 2) % 3, it + 2);
        CP_COMMIT();
        CP_WAIT2();
        __syncthreads();

        const float* As_ = sm + (it % 3) * STG_F;
        const float* Bs_ = As_ + 128 * APAD;
        #pragma unroll
        for (int ks = 0; ks < 2; ks++) {
            const int kk = ks * 8;
            uint32_t af[4][4], bf[4][2];
            #pragma unroll
            for (int mt = 0; mt < 4; mt++) {
                const float* p = As_ + (size_t)(wm * 64 + mt * 16 + lr) * APAD + kk + lc;
                af[mt][0] = __float_as_uint(p[0]);
                af[mt][1] = __float_as_uint(p[8 * APAD]);
                af[mt][2] = __float_as_uint(p[4]);
                af[mt][3] = __float_as_uint(p[8 * APAD + 4]);
            }
            #pragma unroll
            for (int nt = 0; nt < 4; nt++) {
                const float* p = Bs_ + (size_t)(kk + lc) * BPAD + wn * 32 + nt * 8 + lr;
                bf[nt][0] = __float_as_uint(p[0]);
                bf[nt][1] = __float_as_uint(p[4 * BPAD]);
            }
            #pragma unroll
            for (int mt = 0; mt < 4; mt++)
                #pragma unroll
                for (int nt = 0; nt < 4; nt++)
                    mma1688(acc[mt][nt], af[mt], bf[nt]);
        }
        __syncthreads();
    }

    // epilogue
    #pragma unroll
    for (int mt = 0; mt < 4; mt++) {
        #pragma unroll
        for (int nt = 0; nt < 4; nt++) {
            int col = bn + wn * 32 + nt * 8 + lc * 2;
            float2 bv = *(const float2*)(bias + col);
            #pragma unroll
            for (int half = 0; half < 2; half++) {
                size_t row = (size_t)(bm + wm * 64 + mt * 16 + lr + half * 8);
                float v0 = acc[mt][nt][half * 2 + 0] + bv.x;
                float v1 = acc[mt][nt][half * 2 + 1] + bv.y;
                if (EPI == EPI_BIAS_RES) {
                    float2 rv = *(const float2*)(R + row * N + col);
                    v0 += rv.x; v1 += rv.y;
                }
                if (EPI == EPI_BIAS_GELU) {
                    v0 = 0.5f * v0 * (1.f + erff(v0 * 0.7071067811865476f));
                    v1 = 0.5f * v1 * (1.f + erff(v1 * 0.7071067811865476f));
                    v0 = round_tf32(v0);   // feeds next tf32 GEMM
                    v1 = round_tf32(v1);
                }
                float2 o = {v0, v1};
                *(float2*)(C + row * N + col) = o;
            }
        }
    }
}

// ---------------- weight rounding ---------------------------------------------
__global__ void roundw_kernel(const float* __restrict__ in, float* __restrict__ out, int n) {
    int i = blockIdx.x * 256 + threadIdx.x;
    if (i < n) out[i] = round_tf32(in[i]);
}

// ---------------- block reduction (256 threads) --------------------------------
__device__ __forceinline__ float block_sum256(float v) {
    __shared__ float sh[8];
    int lane = threadIdx.x & 31, w = threadIdx.x >> 5;
    #pragma unroll
    for (int o = 16; o > 0; o >>= 1) v += __shfl_down_sync(0xffffffffu, v, o);
    if (lane == 0) sh[w] = v;
    __syncthreads();
    float r = 0.f;
    #pragma unroll
    for (int i = 0; i < 8; i++) r += sh[i];
    __syncthreads();
    return r;
}

// ---------------- LayerNorm (tf32-rounded output) ------------------------------
__global__ void ln_kernel(const float* __restrict__ x, const float* __restrict__ w,
                          const float* __restrict__ bb, float* __restrict__ y) {
    int row = blockIdx.x;
    const float* xr = x + (size_t)row * D_;
    int t = threadIdx.x;
    float v0 = xr[t], v1 = xr[t + 256], v2 = xr[t + 512];
    float s = block_sum256(v0 + v1 + v2);
    float mu = s * (1.f / 768.f);
    float d0 = v0 - mu, d1 = v1 - mu, d2 = v2 - mu;
    float vs = block_sum256(d0 * d0 + d1 * d1 + d2 * d2);
    float rstd = rsqrtf(vs * (1.f / 768.f) + 1e-5f);
    float* yr = y + (size_t)row * D_;
    yr[t]       = round_tf32(d0 * rstd * w[t]       + bb[t]);
    yr[t + 256] = round_tf32(d1 * rstd * w[t + 256] + bb[t + 256]);
    yr[t + 512] = round_tf32(d2 * rstd * w[t + 512] + bb[t + 512]);
}

// ---------------- Attention: flash-style, windowed causal ----------------------
#define PAD68 68
#define ATTN_SMEM_BYTES ((4 * 64 * PAD68 + 3 * 64 + 64) * 4)

__global__ void __launch_bounds__(256) attn_kernel(
    const float* __restrict__ qkv, const int* __restrict__ amask,
    float* __restrict__ out)
{
    extern __shared__ float smf[];
    float* Qt   = smf;
    float* Kt   = Qt + 64 * PAD68;
    float* Vs   = Kt + 64 * PAD68;
    float* St   = Vs + 64 * PAD68;
    float* m_s  = St + 64 * PAD68;
    float* l_s  = m_s + 64;
    float* al_s = l_s + 64;
    int*   kmsk = (int*)(al_s + 64);

    const int qi = blockIdx.x, h = blockIdx.y, b = blockIdx.z;
    const int qb = qi * 64;
    const int tid = threadIdx.x;
    const float scale = 0.125f;

    {
        int d = tid & 63, r0 = tid >> 6;
        const float* qp = qkv + ((size_t)(b * T_ + qb)) * (3 * D_) + h * 64 + d;
        #pragma unroll
        for (int r = r0; r < 64; r += 4)
            Qt[d * PAD68 + r] = qp[(size_t)r * (3 * D_)];
    }
    if (tid < 64) { m_s[tid] = -1e30f; l_s[tid] = 0.f; }

    const int ty = tid >> 4, tx = tid & 15;
    const int q0 = ty * 4, k0 = tx * 4;
    float o[4][4];
    #pragma unroll
    for (int i = 0; i < 4; i++)
        #pragma unroll
        for (int j = 0; j < 4; j++) o[i][j] = 0.f;

    int jlo = qb - (WIN_ - 1);
    int kt0 = (jlo > 0 ? jlo : 0) >> 6;

    for (int kt = kt0; kt <= qi; kt++) {
        const int kb = kt * 64;
        __syncthreads();
        {
            int d = tid & 63, r0 = tid >> 6;
            const float* kp = qkv + ((size_t)(b * T_ + kb)) * (3 * D_) + D_ + h * 64;
            const float* vp = kp + D_;
            #pragma unroll
            for (int r = r0; r < 64; r += 4) {
                Kt[d * PAD68 + r] = kp[(size_t)r * (3 * D_) + d];
                Vs[r * PAD68 + d] = vp[(size_t)r * (3 * D_) + d];
            }
            if (tid < 64) kmsk[tid] = amask[b * T_ + kb + tid];
        }
        __syncthreads();

        float acc[4][4];
        #pragma unroll
        for (int i = 0; i < 4; i++)
            #pragma unroll
            for (int j = 0; j < 4; j++) acc[i][j] = 0.f;
        #pragma unroll 8
        for (int d = 0; d < 64; d++) {
            float4 qv = *(const float4*)(&Qt[d * PAD68 + q0]);
            float4 kv = *(const float4*)(&Kt[d * PAD68 + k0]);
            float qa[4] = {qv.x, qv.y, qv.z, qv.w};
            float ka[4] = {kv.x, kv.y, kv.z, kv.w};
            #pragma unroll
            for (int i = 0; i < 4; i++)
                #pragma unroll
                for (int j = 0; j < 4; j++)
                    acc[i][j] = fmaf(qa[i], ka[j], acc[i][j]);
        }
        #pragma unroll
        for (int jj = 0; jj < 4; jj++) {
            int j = kb + k0 + jj;
            int km = kmsk[k0 + jj];
            #pragma unroll
            for (int ii = 0; ii < 4; ii++) {
                int i = qb + q0 + ii;
                bool valid = (j <= i) && (j > i - WIN_) && (km != 0);
                St[(k0 + jj) * PAD68 + q0 + ii] = valid ? acc[ii][jj] * scale : -1e30f;
            }
        }
        __syncthreads();

        if (tid < 64) {
            int q = tid;
            float m_old = m_s[q];
            float mt = m_old;
            for (int k = 0; k < 64; k++) mt = fmaxf(mt, St[k * PAD68 + q]);
            float alpha = __expf(m_old - mt);
            float lsum = 0.f;
            for (int k = 0; k < 64; k++) {
                float s = St[k * PAD68 + q];
                float p = (s <= -1e29f) ? 0.f : __expf(s - mt);
                St[k * PAD68 + q] = p;
                lsum += p;
            }
            m_s[q] = mt;
            l_s[q] = l_s[q] * alpha + lsum;
            al_s[q] = alpha;
        }
        __syncthreads();

        float alv[4];
        #pragma unroll
        for (int ii = 0; ii < 4; ii++) alv[ii] = al_s[q0 + ii];
        #pragma unroll
        for (int ii = 0; ii < 4; ii++)
            #pragma unroll
            for (int jj = 0; jj < 4; jj++) o[ii][jj] *= alv[ii];
        #pragma unroll 8
        for (int k = 0; k < 64; k++) {
            float4 pv = *(const float4*)(&St[k * PAD68 + q0]);
            float4 vv = *(const float4*)(&Vs[k * PAD68 + k0]);
            float pa[4] = {pv.x, pv.y, pv.z, pv.w};
            float va[4] = {vv.x, vv.y, vv.z, vv.w};
            #pragma unroll
            for (int ii = 0; ii < 4; ii++)
                #pragma unroll
                for (int jj = 0; jj < 4; jj++)
                    o[ii][jj] = fmaf(pa[ii], va[jj], o[ii][jj]);
        }
    }

    __syncthreads();
    float linv[4];
    #pragma unroll
    for (int ii = 0; ii < 4; ii++) linv[ii] = 1.f / l_s[q0 + ii];
    #pragma unroll
    for (int ii = 0; ii < 4; ii++) {
        float4 r4 = {round_tf32(o[ii][0] * linv[ii]), round_tf32(o[ii][1] * linv[ii]),
                     round_tf32(o[ii][2] * linv[ii]), round_tf32(o[ii][3] * linv[ii])};
        *(float4*)(out + ((size_t)(b * T_ + qb + q0 + ii)) * D_ + h * 64 + tx * 4) = r4;
    }
}

// ---------------- launch --------------------------------------------------------
extern "C" void kernel_launch(void* const* d_in, const int* in_sizes, int n_in,
                              void* d_out, int out_size)
{
    const float* x      = (const float*)d_in[0];
    const int*   amask  = (const int*)d_in[1];
    const float* ln1_w  = (const float*)d_in[2];
    const float* ln1_b  = (const float*)d_in[3];
    const float* w_attn = (const float*)d_in[4];
    const float* b_attn = (const float*)d_in[5];
    const float* w_proj = (const float*)d_in[6];
    const float* b_proj = (const float*)d_in[7];
    const float* ln2_w  = (const float*)d_in[8];
    const float* ln2_b  = (const float*)d_in[9];
    const float* w_fc   = (const float*)d_in[10];
    const float* b_fc   = (const float*)d_in[11];
    const float* w_fcp  = (const float*)d_in[12];
    const float* b_fcp  = (const float*)d_in[13];
    float* out = (float*)d_out;

    float *p_x1, *p_qkv, *p_attn, *p_x2, *p_h;
    float *p_w_attn, *p_w_proj, *p_w_fc, *p_w_fcp;
    cudaGetSymbolAddress((void**)&p_x1,     g_x1);
    cudaGetSymbolAddress((void**)&p_qkv,    g_qkv);
    cudaGetSymbolAddress((void**)&p_attn,   g_attn);
    cudaGetSymbolAddress((void**)&p_x2,     g_x2);
    cudaGetSymbolAddress((void**)&p_h,      g_h);
    cudaGetSymbolAddress((void**)&p_w_attn, g_w_attn);
    cudaGetSymbolAddress((void**)&p_w_proj, g_w_proj);
    cudaGetSymbolAddress((void**)&p_w_fc,   g_w_fc);
    cudaGetSymbolAddress((void**)&p_w_fcp,  g_w_fcp);

    cudaFuncSetAttribute(mma_gemm<EPI_BIAS>,      cudaFuncAttributeMaxDynamicSharedMemorySize, GEMM_SMEM);
    cudaFuncSetAttribute(mma_gemm<EPI_BIAS_RES>,  cudaFuncAttributeMaxDynamicSharedMemorySize, GEMM_SMEM);
    cudaFuncSetAttribute(mma_gemm<EPI_BIAS_GELU>, cudaFuncAttributeMaxDynamicSharedMemorySize, GEMM_SMEM);
    cudaFuncSetAttribute(attn_kernel, cudaFuncAttributeMaxDynamicSharedMemorySize, ATTN_SMEM_BYTES);

    // round weights to tf32 once
    roundw_kernel<<<(768 * 2304 + 255) / 256, 256>>>(w_attn, p_w_attn, 768 * 2304);
    roundw_kernel<<<(768 * 768 + 255) / 256, 256>>>(w_proj, p_w_proj, 768 * 768);
    roundw_kernel<<<(768 * 3072 + 255) / 256, 256>>>(w_fc, p_w_fc, 768 * 3072);
    roundw_kernel<<<(3072 * 768 + 255) / 256, 256>>>(w_fcp, p_w_fcp, 3072 * 768);

    // 1) ln1
    ln_kernel<<<M_, 256>>>(x, ln1_w, ln1_b, p_x1);
    // 2) qkv = x1 @ w_attn + b_attn   [8192 x 2304 x 768]
    mma_gemm<EPI_BIAS><<<dim3(2304 / 128, M_ / 128), 256, GEMM_SMEM>>>(
        p_x1, p_w_attn, b_attn, nullptr, p_qkv, 2304, 768);
    // 3) attention
    attn_kernel<<<dim3(T_ / 64, H_, B_), 256, ATTN_SMEM_BYTES>>>(p_qkv, amask, p_attn);
    // 4) x2 = attn @ w_proj + b_proj + x   [8192 x 768 x 768]
    mma_gemm<EPI_BIAS_RES><<<dim3(768 / 128, M_ / 128), 256, GEMM_SMEM>>>(
        p_attn, p_w_proj, b_proj, x, p_x2, 768, 768);
    // 5) ln2
    ln_kernel<<<M_, 256>>>(p_x2, ln2_w, ln2_b, p_x1);
    // 6) h = gelu(x1 @ w_fc + b_fc)   [8192 x 3072 x 768]
    mma_gemm<EPI_BIAS_GELU><<<dim3(3072 / 128, M_ / 128), 256, GEMM_SMEM>>>(
        p_x1, p_w_fc, b_fc, nullptr, p_h, 3072, 768);
    // 7) out = h @ w_fc_proj + b_fc_proj + x2   [8192 x 768 x 3072]
    mma_gemm<EPI_BIAS_RES><<<dim3(768 / 128, M_ / 128), 256, GEMM_SMEM>>>(
        p_h, p_w_fcp, b_fcp, p_x2, out, 768, 3072);
}

// round 4
// speedup vs baseline: 2.7394x; 1.2539x over previous
#include <cuda_runtime.h>
#include <math.h>
#include <stdint.h>

#define B_   8
#define T_   1024
#define D_   768
#define H_   12
#define WIN_ 768
#define M_   (B_*T_)   // 8192

// ---------------- scratch (static device globals) ---------------------------
__device__ float g_x1[M_ * D_];
__device__ float g_qkv[M_ * 3 * D_];
__device__ float g_attn[M_ * D_];
__device__ float g_x2[M_ * D_];
__device__ float g_h[M_ * 4 * D_];
__device__ float g_w_attn[D_ * 3 * D_];
__device__ float g_w_proj[D_ * D_];
__device__ float g_w_fc[D_ * 4 * D_];
__device__ float g_w_fcp[4 * D_ * D_];

// ---------------- helpers -----------------------------------------------------
__device__ __forceinline__ uint32_t smem_to_u32(const void* p) {
    uint32_t a;
    asm("{ .reg .u64 t; cvta.to.shared.u64 t, %1; cvt.u32.u64 %0, t; }" : "=r"(a) : "l"(p));
    return a;
}
__device__ __forceinline__ float round_tf32(float v) {
    uint32_t o;
    asm("cvt.rna.tf32.f32 %0, %1;" : "=r"(o) : "f"(v));
    return __uint_as_float(o);
}
#define CP16(saddr, gptr) \
    asm volatile("cp.async.cg.shared.global [%0], [%1], 16;" :: "r"(saddr), "l"(gptr))
#define CP_COMMIT() asm volatile("cp.async.commit_group;" ::: "memory")
#define CP_WAIT2()  asm volatile("cp.async.wait_group 2;" ::: "memory")

__device__ __forceinline__ void mma1688(float* d, const uint32_t* a, const uint32_t* b) {
    asm volatile(
        "mma.sync.aligned.m16n8k8.row.col.f32.tf32.tf32.f32 "
        "{%0,%1,%2,%3}, {%4,%5,%6,%7}, {%8,%9}, {%0,%1,%2,%3};"
        : "+f"(d[0]), "+f"(d[1]), "+f"(d[2]), "+f"(d[3])
        : "r"(a[0]), "r"(a[1]), "r"(a[2]), "r"(a[3]), "r"(b[0]), "r"(b[1]));
}

// ---------------- tf32 tensor-core GEMM ---------------------------------------
enum { EPI_BIAS = 0, EPI_BIAS_RES = 1, EPI_BIAS_GELU = 2 };

#define APAD 20
#define BPAD 136
#define STG_F (128 * APAD + 16 * BPAD)
#define GEMM_SMEM (3 * STG_F * 4)

template <int EPI>
__global__ void __launch_bounds__(256, 2) mma_gemm(
    const float* __restrict__ A, const float* __restrict__ W,
    const float* __restrict__ bias, const float* __restrict__ R,
    float* __restrict__ C, int N, int K)
{
    extern __shared__ float sm[];
    const int tid = threadIdx.x;
    const int wid = tid >> 5, lane = tid & 31;
    const int wm = wid >> 2, wn = wid & 3;
    const int bm = blockIdx.y << 7, bn = blockIdx.x << 7;
    const int lr = lane >> 2, lc = lane & 3;
    const int NIT = K >> 4;

    const int am = tid >> 1, ac = tid & 1;
    const int br = tid >> 4, bc = tid & 15;
    const float* gA = A + (size_t)(bm + am) * K;
    const float* gB = W + (size_t)br * N + bn;

    float acc[4][4][4];
    #pragma unroll
    for (int i = 0; i < 4; i++)
        #pragma unroll
        for (int j = 0; j < 4; j++)
            #pragma unroll
            for (int k = 0; k < 4; k++) acc[i][j][k] = 0.f;

    auto load_stage = [&](int s, int kt) {
        float* As_ = sm + s * STG_F;
        float* Bs_ = As_ + 128 * APAD;
        uint32_t sa = smem_to_u32(As_ + am * APAD);
        const float* ga = gA + (kt << 4);
        CP16(sa + (ac * 4) * 4,       ga + ac * 4);
        CP16(sa + ((ac + 2) * 4) * 4, ga + (ac + 2) * 4);
        uint32_t sb = smem_to_u32(Bs_ + br * BPAD);
        const float* gb = gB + (size_t)(kt << 4) * N;
        CP16(sb + (bc * 4) * 4,        gb + bc * 4);
        CP16(sb + ((bc + 16) * 4) * 4, gb + (bc + 16) * 4);
    };

    load_stage(0, 0); CP_COMMIT();
    load_stage(1, 1); CP_COMMIT();

    for (int it = 0; it < NIT; it++) {
        if (it + 2 < NIT) load_stage((it + 2) % 3, it + 2);
        CP_COMMIT();
        CP_WAIT2();
        __syncthreads();

        const float* As_ = sm + (it % 3) * STG_F;
        const float* Bs_ = As_ + 128 * APAD;
        #pragma unroll
        for (int ks = 0; ks < 2; ks++) {
            const int kk = ks * 8;
            uint32_t af[4][4], bf[4][2];
            #pragma unroll
            for (int mt = 0; mt < 4; mt++) {
                const float* p = As_ + (size_t)(wm * 64 + mt * 16 + lr) * APAD + kk + lc;
                af[mt][0] = __float_as_uint(p[0]);
                af[mt][1] = __float_as_uint(p[8 * APAD]);
                af[mt][2] = __float_as_uint(p[4]);
                af[mt][3] = __float_as_uint(p[8 * APAD + 4]);
            }
            #pragma unroll
            for (int nt = 0; nt < 4; nt++) {
                const float* p = Bs_ + (size_t)(kk + lc) * BPAD + wn * 32 + nt * 8 + lr;
                bf[nt][0] = __float_as_uint(p[0]);
                bf[nt][1] = __float_as_uint(p[4 * BPAD]);
            }
            #pragma unroll
            for (int mt = 0; mt < 4; mt++)
                #pragma unroll
                for (int nt = 0; nt < 4; nt++)
                    mma1688(acc[mt][nt], af[mt], bf[nt]);
        }
        __syncthreads();
    }

    #pragma unroll
    for (int mt = 0; mt < 4; mt++) {
        #pragma unroll
        for (int nt = 0; nt < 4; nt++) {
            int col = bn + wn * 32 + nt * 8 + lc * 2;
            float2 bv = *(const float2*)(bias + col);
            #pragma unroll
            for (int half = 0; half < 2; half++) {
                size_t row = (size_t)(bm + wm * 64 + mt * 16 + lr + half * 8);
                float v0 = acc[mt][nt][half * 2 + 0] + bv.x;
                float v1 = acc[mt][nt][half * 2 + 1] + bv.y;
                if (EPI == EPI_BIAS_RES) {
                    float2 rv = *(const float2*)(R + row * N + col);
                    v0 += rv.x; v1 += rv.y;
                }
                if (EPI == EPI_BIAS_GELU) {
                    v0 = 0.5f * v0 * (1.f + erff(v0 * 0.7071067811865476f));
                    v1 = 0.5f * v1 * (1.f + erff(v1 * 0.7071067811865476f));
                    v0 = round_tf32(v0);
                    v1 = round_tf32(v1);
                }
                float2 o = {v0, v1};
                *(float2*)(C + row * N + col) = o;
            }
        }
    }
}

// ---------------- weight rounding ---------------------------------------------
__global__ void roundw_kernel(const float* __restrict__ in, float* __restrict__ out, int n) {
    int i = blockIdx.x * 256 + threadIdx.x;
    if (i < n) out[i] = round_tf32(in[i]);
}

// ---------------- block reduction (256 threads) --------------------------------
__device__ __forceinline__ float block_sum256(float v) {
    __shared__ float sh[8];
    int lane = threadIdx.x & 31, w = threadIdx.x >> 5;
    #pragma unroll
    for (int o = 16; o > 0; o >>= 1) v += __shfl_down_sync(0xffffffffu, v, o);
    if (lane == 0) sh[w] = v;
    __syncthreads();
    float r = 0.f;
    #pragma unroll
    for (int i = 0; i < 8; i++) r += sh[i];
    __syncthreads();
    return r;
}

// ---------------- LayerNorm (tf32-rounded output) ------------------------------
__global__ void ln_kernel(const float* __restrict__ x, const float* __restrict__ w,
                          const float* __restrict__ bb, float* __restrict__ y) {
    int row = blockIdx.x;
    const float* xr = x + (size_t)row * D_;
    int t = threadIdx.x;
    float v0 = xr[t], v1 = xr[t + 256], v2 = xr[t + 512];
    float s = block_sum256(v0 + v1 + v2);
    float mu = s * (1.f / 768.f);
    float d0 = v0 - mu, d1 = v1 - mu, d2 = v2 - mu;
    float vs = block_sum256(d0 * d0 + d1 * d1 + d2 * d2);
    float rstd = rsqrtf(vs * (1.f / 768.f) + 1e-5f);
    float* yr = y + (size_t)row * D_;
    yr[t]       = round_tf32(d0 * rstd * w[t]       + bb[t]);
    yr[t + 256] = round_tf32(d1 * rstd * w[t + 256] + bb[t + 256]);
    yr[t + 512] = round_tf32(d2 * rstd * w[t + 512] + bb[t + 512]);
}

// ---------------- Attention: tensor-core flash, windowed causal ----------------
// q-tile 128 (8 warps x 16 rows), key-tile 64, HD=64. All MMAs m16n8k8 tf32.
#define TQ 128
#define KP 68     // Kn[key][d] stride
#define VP 72     // Vs[key][d] stride
#define SP 68     // St[q][key] stride (also Q staging [q][d])
#define ATTN_SMEM_BYTES ((64 * KP + 64 * VP + TQ * SP + 64) * 4)

__global__ void __launch_bounds__(256, 2) attn_mma_kernel(
    const float* __restrict__ qkv, const int* __restrict__ amask,
    float* __restrict__ out)
{
    extern __shared__ float smf[];
    float* Kn = smf;                 // [64][KP]  key-major K
    float* Vs = Kn + 64 * KP;        // [64][VP]  key-major V
    float* St = Vs + 64 * VP;        // [TQ][SP]  P (and Q staging)
    int* kmsk = (int*)(St + TQ * SP);

    const int qi = blockIdx.x, h = blockIdx.y, b = blockIdx.z;
    const int qb = qi * TQ;
    const int tid = threadIdx.x, wid = tid >> 5, lane = tid & 31;
    const int lr = lane >> 2, lc = lane & 3;
    const int wq = wid * 16;

    // ---- stage Q tile into St, then pull fragments (scaled) ----
    {
        int r = tid >> 4, dq = (tid & 15) * 4;
        #pragma unroll
        for (int rr = r; rr < TQ; rr += 16) {
            const float* src = qkv + ((size_t)(b * T_ + qb + rr)) * (3 * D_) + h * 64 + dq;
            *(float4*)(St + rr * SP + dq) = *(const float4*)src;
        }
    }
    __syncthreads();
    uint32_t qa[8][4];
    #pragma unroll
    for (int kk = 0; kk < 8; kk++) {
        const float* p = St + (size_t)(wq + lr) * SP + kk * 8 + lc;
        qa[kk][0] = __float_as_uint(p[0] * 0.125f);
        qa[kk][1] = __float_as_uint(p[8 * SP] * 0.125f);
        qa[kk][2] = __float_as_uint(p[4] * 0.125f);
        qa[kk][3] = __float_as_uint(p[8 * SP + 4] * 0.125f);
    }

    float o[8][4];
    #pragma unroll
    for (int j = 0; j < 8; j++)
        #pragma unroll
        for (int k = 0; k < 4; k++) o[j][k] = 0.f;
    float mrow[2] = {-1e30f, -1e30f}, lrow[2] = {0.f, 0.f};

    int lo = qb - (WIN_ - 1);
    const int kt0 = (lo > 0 ? lo : 0) >> 6;
    const int kt1 = (qb + TQ - 1) >> 6;

    for (int kt = kt0; kt <= kt1; kt++) {
        const int kb = kt * 64;
        __syncthreads();
        {
            int r = tid >> 4, dq = (tid & 15) * 4;
            const float* kpb = qkv + ((size_t)(b * T_ + kb)) * (3 * D_) + D_ + h * 64;
            #pragma unroll
            for (int rr = r; rr < 64; rr += 16) {
                const float* src = kpb + (size_t)rr * (3 * D_) + dq;
                *(float4*)(Kn + rr * KP + dq) = *(const float4*)src;
                *(float4*)(Vs + rr * VP + dq) = *(const float4*)(src + D_);
            }
            if (tid < 64) kmsk[tid] = amask[b * T_ + kb + tid];
        }
        __syncthreads();

        // S = (Q*scale) K^T   (per warp: 16 x 64)
        float sc[8][4];
        #pragma unroll
        for (int j = 0; j < 8; j++) {
            sc[j][0] = sc[j][1] = sc[j][2] = sc[j][3] = 0.f;
            #pragma unroll
            for (int kk = 0; kk < 8; kk++) {
                const float* p = Kn + (size_t)(j * 8 + lr) * KP + kk * 8 + lc;
                uint32_t bf[2] = {__float_as_uint(p[0]), __float_as_uint(p[4])};
                mma1688(sc[j], qa[kk], bf);
            }
        }

        // mask
        #pragma unroll
        for (int j = 0; j < 8; j++) {
            int kg0 = kb + j * 8 + lc * 2, kg1 = kg0 + 1;
            int km0 = kmsk[j * 8 + lc * 2], km1 = kmsk[j * 8 + lc * 2 + 1];
            #pragma unroll
            for (int half = 0; half < 2; half++) {
                int qg = qb + wq + lr + half * 8;
                bool v0 = (kg0 <= qg) && (kg0 > qg - WIN_) && (km0 != 0);
                bool v1 = (kg1 <= qg) && (kg1 > qg - WIN_) && (km1 != 0);
                if (!v0) sc[j][half * 2 + 0] = -1e30f;
                if (!v1) sc[j][half * 2 + 1] = -1e30f;
            }
        }

        // online softmax (quad reductions)
        float mnew[2], alpha[2], lsum[2];
        #pragma unroll
        for (int half = 0; half < 2; half++) {
            float m = -1e30f;
            #pragma unroll
            for (int j = 0; j < 8; j++)
                m = fmaxf(m, fmaxf(sc[j][half * 2], sc[j][half * 2 + 1]));
            m = fmaxf(m, __shfl_xor_sync(0xffffffffu, m, 1));
            m = fmaxf(m, __shfl_xor_sync(0xffffffffu, m, 2));
            mnew[half] = fmaxf(mrow[half], m);
            alpha[half] = __expf(mrow[half] - mnew[half]);
            lsum[half] = 0.f;
        }
        #pragma unroll
        for (int j = 0; j < 8; j++) {
            #pragma unroll
            for (int half = 0; half < 2; half++) {
                float s0 = sc[j][half * 2], s1 = sc[j][half * 2 + 1];
                float p0 = (s0 <= -1e29f) ? 0.f : __expf(s0 - mnew[half]);
                float p1 = (s1 <= -1e29f) ? 0.f : __expf(s1 - mnew[half]);
                sc[j][half * 2] = p0; sc[j][half * 2 + 1] = p1;
                lsum[half] += p0 + p1;
            }
        }
        #pragma unroll
        for (int half = 0; half < 2; half++) {
            lsum[half] += __shfl_xor_sync(0xffffffffu, lsum[half], 1);
            lsum[half] += __shfl_xor_sync(0xffffffffu, lsum[half], 2);
            lrow[half] = lrow[half] * alpha[half] + lsum[half];
            mrow[half] = mnew[half];
        }
        #pragma unroll
        for (int j = 0; j < 8; j++) {
            o[j][0] *= alpha[0]; o[j][1] *= alpha[0];
            o[j][2] *= alpha[1]; o[j][3] *= alpha[1];
        }

        // write P to St (warp-private rows)
        #pragma unroll
        for (int j = 0; j < 8; j++) {
            float2 p0 = {sc[j][0], sc[j][1]};
            float2 p1 = {sc[j][2], sc[j][3]};
            *(float2*)(St + (size_t)(wq + lr) * SP + j * 8 + lc * 2) = p0;
            *(float2*)(St + (size_t)(wq + lr + 8) * SP + j * 8 + lc * 2) = p1;
        }
        __syncwarp();

        // O += P V   (per warp: 16 x 64)
        #pragma unroll
        for (int kk = 0; kk < 8; kk++) {
            const float* pa = St + (size_t)(wq + lr) * SP + kk * 8 + lc;
            const float* pb = St + (size_t)(wq + lr + 8) * SP + kk * 8 + lc;
            uint32_t af[4] = {__float_as_uint(pa[0]), __float_as_uint(pb[0]),
                              __float_as_uint(pa[4]), __float_as_uint(pb[4])};
            #pragma unroll
            for (int j = 0; j < 8; j++) {
                const float* p = Vs + (size_t)(kk * 8 + lc) * VP + j * 8 + lr;
                uint32_t bf[2] = {__float_as_uint(p[0]), __float_as_uint(p[4 * VP])};
                mma1688(o[j], af, bf);
            }
        }
    }

    // normalize + write
    float linv[2] = {1.f / lrow[0], 1.f / lrow[1]};
    #pragma unroll
    for (int half = 0; half < 2; half++) {
        size_t row = (size_t)(b * T_ + qb + wq + lr + half * 8);
        float* op = out + row * D_ + h * 64;
        #pragma unroll
        for (int j = 0; j < 8; j++) {
            float2 r2 = {round_tf32(o[j][half * 2] * linv[half]),
                         round_tf32(o[j][half * 2 + 1] * linv[half])};
            *(float2*)(op + j * 8 + lc * 2) = r2;
        }
    }
}

// ---------------- launch --------------------------------------------------------
extern "C" void kernel_launch(void* const* d_in, const int* in_sizes, int n_in,
                              void* d_out, int out_size)
{
    const float* x      = (const float*)d_in[0];
    const int*   amask  = (const int*)d_in[1];
    const float* ln1_w  = (const float*)d_in[2];
    const float* ln1_b  = (const float*)d_in[3];
    const float* w_attn = (const float*)d_in[4];
    const float* b_attn = (const float*)d_in[5];
    const float* w_proj = (const float*)d_in[6];
    const float* b_proj = (const float*)d_in[7];
    const float* ln2_w  = (const float*)d_in[8];
    const float* ln2_b  = (const float*)d_in[9];
    const float* w_fc   = (const float*)d_in[10];
    const float* b_fc   = (const float*)d_in[11];
    const float* w_fcp  = (const float*)d_in[12];
    const float* b_fcp  = (const float*)d_in[13];
    float* out = (float*)d_out;

    float *p_x1, *p_qkv, *p_attn, *p_x2, *p_h;
    float *p_w_attn, *p_w_proj, *p_w_fc, *p_w_fcp;
    cudaGetSymbolAddress((void**)&p_x1,     g_x1);
    cudaGetSymbolAddress((void**)&p_qkv,    g_qkv);
    cudaGetSymbolAddress((void**)&p_attn,   g_attn);
    cudaGetSymbolAddress((void**)&p_x2,     g_x2);
    cudaGetSymbolAddress((void**)&p_h,      g_h);
    cudaGetSymbolAddress((void**)&p_w_attn, g_w_attn);
    cudaGetSymbolAddress((void**)&p_w_proj, g_w_proj);
    cudaGetSymbolAddress((void**)&p_w_fc,   g_w_fc);
    cudaGetSymbolAddress((void**)&p_w_fcp,  g_w_fcp);

    cudaFuncSetAttribute(mma_gemm<EPI_BIAS>,      cudaFuncAttributeMaxDynamicSharedMemorySize, GEMM_SMEM);
    cudaFuncSetAttribute(mma_gemm<EPI_BIAS_RES>,  cudaFuncAttributeMaxDynamicSharedMemorySize, GEMM_SMEM);
    cudaFuncSetAttribute(mma_gemm<EPI_BIAS_GELU>, cudaFuncAttributeMaxDynamicSharedMemorySize, GEMM_SMEM);
    cudaFuncSetAttribute(attn_mma_kernel, cudaFuncAttributeMaxDynamicSharedMemorySize, ATTN_SMEM_BYTES);

    roundw_kernel<<<(768 * 2304 + 255) / 256, 256>>>(w_attn, p_w_attn, 768 * 2304);
    roundw_kernel<<<(768 * 768 + 255) / 256, 256>>>(w_proj, p_w_proj, 768 * 768);
    roundw_kernel<<<(768 * 3072 + 255) / 256, 256>>>(w_fc, p_w_fc, 768 * 3072);
    roundw_kernel<<<(3072 * 768 + 255) / 256, 256>>>(w_fcp, p_w_fcp, 3072 * 768);

    // 1) ln1
    ln_kernel<<<M_, 256>>>(x, ln1_w, ln1_b, p_x1);
    // 2) qkv = x1 @ w_attn + b_attn   [8192 x 2304 x 768]
    mma_gemm<EPI_BIAS><<<dim3(2304 / 128, M_ / 128), 256, GEMM_SMEM>>>(
        p_x1, p_w_attn, b_attn, nullptr, p_qkv, 2304, 768);
    // 3) attention (tensor-core flash)
    attn_mma_kernel<<<dim3(T_ / TQ, H_, B_), 256, ATTN_SMEM_BYTES>>>(p_qkv, amask, p_attn);
    // 4) x2 = attn @ w_proj + b_proj + x   [8192 x 768 x 768]
    mma_gemm<EPI_BIAS_RES><<<dim3(768 / 128, M_ / 128), 256, GEMM_SMEM>>>(
        p_attn, p_w_proj, b_proj, x, p_x2, 768, 768);
    // 5) ln2
    ln_kernel<<<M_, 256>>>(p_x2, ln2_w, ln2_b, p_x1);
    // 6) h = gelu(x1 @ w_fc + b_fc)   [8192 x 3072 x 768]
    mma_gemm<EPI_BIAS_GELU><<<dim3(3072 / 128, M_ / 128), 256, GEMM_SMEM>>>(
        p_x1, p_w_fc, b_fc, nullptr, p_h, 3072, 768);
    // 7) out = h @ w_fc_proj + b_fc_proj + x2   [8192 x 768 x 3072]
    mma_gemm<EPI_BIAS_RES><<<dim3(768 / 128, M_ / 128), 256, GEMM_SMEM>>>(
        p_h, p_w_fcp, b_fcp, p_x2, out, 768, 3072);
}

// round 5
// speedup vs baseline: 4.9951x; 1.8235x over previous
#include <cuda_runtime.h>
#include <cuda_fp16.h>
#include <math.h>
#include <stdint.h>

#define B_   8
#define T_   1024
#define D_   768
#define H_   12
#define WIN_ 768
#define M_   (B_*T_)   // 8192

// ---------------- scratch (static device globals) ---------------------------
__device__ __half g_x1h[M_ * D_];
__device__ __half g_qkvh[M_ * 3 * D_];
__device__ __half g_attnh[M_ * D_];
__device__ float  g_x2[M_ * D_];
__device__ __half g_hh[M_ * 4 * D_];
__device__ __half g_wah[D_ * 3 * D_];
__device__ __half g_wph[D_ * D_];
__device__ __half g_wfh[D_ * 4 * D_];
__device__ __half g_wfph[4 * D_ * D_];

// ---------------- helpers -----------------------------------------------------
__device__ __forceinline__ uint32_t smem_to_u32(const void* p) {
    uint32_t a;
    asm("{ .reg .u64 t; cvta.to.shared.u64 t, %1; cvt.u32.u64 %0, t; }" : "=r"(a) : "l"(p));
    return a;
}
__device__ __forceinline__ uint32_t h2u(__half2 v) { return *(uint32_t*)&v; }

#define CP16(saddr, gptr) \
    asm volatile("cp.async.cg.shared.global [%0], [%1], 16;" :: "r"(saddr), "l"(gptr))
#define CP_COMMIT() asm volatile("cp.async.commit_group;" ::: "memory")
#define CP_WAIT2()  asm volatile("cp.async.wait_group 2;" ::: "memory")

#define LDSM4T(r0, r1, r2, r3, addr) \
    asm volatile("ldmatrix.sync.aligned.m8n8.x4.trans.shared.b16 {%0,%1,%2,%3}, [%4];" \
        : "=r"(r0), "=r"(r1), "=r"(r2), "=r"(r3) : "r"(addr))

__device__ __forceinline__ void mma1616(float* d, const uint32_t* a, const uint32_t* b) {
    asm volatile(
        "mma.sync.aligned.m16n8k16.row.col.f32.f16.f16.f32 "
        "{%0,%1,%2,%3}, {%4,%5,%6,%7}, {%8,%9}, {%0,%1,%2,%3};"
        : "+f"(d[0]), "+f"(d[1]), "+f"(d[2]), "+f"(d[3])
        : "r"(a[0]), "r"(a[1]), "r"(a[2]), "r"(a[3]), "r"(b[0]), "r"(b[1]));
}

// ---------------- fp16 tensor-core GEMM ----------------------------------------
// C[M,N] = A[M,K] @ W[K,N] + bias (+res / gelu). A, W fp16; accum fp32.
// 128x128 tile, BK=32, 8 warps (64x32 each), 3-stage cp.async pipeline.
enum { EPI_BIAS = 0, EPI_BIAS_RES = 1, EPI_BIAS_GELU = 2 };

#define APADH 40                       // A tile row stride (halves)
#define BPADH 136                      // B tile row stride (halves)
#define A_ST (128 * APADH)             // 5120 halves
#define B_ST (32 * BPADH)              // 4352 halves
#define STG_H (A_ST + B_ST)            // 9472 halves
#define GEMM_SMEM (3 * STG_H * 2)      // 56832 bytes

template <int EPI, bool OUTH>
__global__ void __launch_bounds__(256, 2) hgemm(
    const __half* __restrict__ A, const __half* __restrict__ W,
    const float* __restrict__ bias, const float* __restrict__ R,
    float* __restrict__ Cf, __half* __restrict__ Ch, int N, int K)
{
    extern __shared__ char dynsm[];
    __half* smh = (__half*)dynsm;
    const int tid = threadIdx.x;
    const int wid = tid >> 5, lane = tid & 31;
    const int wm = wid >> 2, wn = wid & 3;
    const int bm = blockIdx.y << 7, bn = blockIdx.x << 7;
    const int lr = lane >> 2, lc = lane & 3;
    const int sel = lane >> 3;
    const int brow = (sel & 1) * 8 + (lane & 7);
    const int bcol = (sel >> 1) * 8;
    const int NIT = K >> 5;

    const int am = tid >> 1, ac = tid & 1;     // A: row, half-row
    const int br = tid >> 4, bc = tid & 15;    // B: rows br/br+16, col chunk
    const __half* gA = A + (size_t)(bm + am) * K;
    const __half* gB = W + (size_t)br * N + bn;

    float acc[4][4][4];
    #pragma unroll
    for (int i = 0; i < 4; i++)
        #pragma unroll
        for (int j = 0; j < 4; j++)
            #pragma unroll
            for (int k = 0; k < 4; k++) acc[i][j][k] = 0.f;

    auto load_stage = [&](int s, int kt) {
        __half* Ah = smh + s * STG_H;
        __half* Bh = Ah + A_ST;
        uint32_t sa = smem_to_u32(Ah + am * APADH + ac * 16);
        const __half* ga = gA + (kt << 5) + ac * 16;
        CP16(sa, ga);
        CP16(sa + 16, ga + 8);
        uint32_t sb = smem_to_u32(Bh + br * BPADH + bc * 8);
        const __half* gb = gB + (size_t)(kt << 5) * N + bc * 8;
        CP16(sb, gb);
        CP16(sb + 16 * BPADH * 2, gb + (size_t)16 * N);
    };

    load_stage(0, 0); CP_COMMIT();
    load_stage(1, 1); CP_COMMIT();

    for (int it = 0; it < NIT; it++) {
        if (it + 2 < NIT) load_stage((it + 2) % 3, it + 2);
        CP_COMMIT();
        CP_WAIT2();
        __syncthreads();

        const __half* Ah = smh + (it % 3) * STG_H;
        const __half* Bh = Ah + A_ST;
        const uint32_t bbase = smem_to_u32(Bh);
        #pragma unroll
        for (int kk = 0; kk < 2; kk++) {
            uint32_t bfr[4][2];
            #pragma unroll
            for (int ntp = 0; ntp < 2; ntp++) {
                uint32_t addr = bbase +
                    ((kk * 16 + brow) * BPADH + wn * 32 + ntp * 16 + bcol) * 2;
                LDSM4T(bfr[ntp * 2][0], bfr[ntp * 2][1],
                       bfr[ntp * 2 + 1][0], bfr[ntp * 2 + 1][1], addr);
            }
            #pragma unroll
            for (int mt = 0; mt < 4; mt++) {
                const __half* p = Ah + (size_t)(wm * 64 + mt * 16 + lr) * APADH + kk * 16 + lc * 2;
                uint32_t af[4];
                af[0] = *(const uint32_t*)p;
                af[1] = *(const uint32_t*)(p + 8 * APADH);
                af[2] = *(const uint32_t*)(p + 8);
                af[3] = *(const uint32_t*)(p + 8 * APADH + 8);
                #pragma unroll
                for (int nt = 0; nt < 4; nt++)
                    mma1616(acc[mt][nt], af, bfr[nt]);
            }
        }
        __syncthreads();
    }

    // epilogue
    #pragma unroll
    for (int mt = 0; mt < 4; mt++) {
        #pragma unroll
        for (int nt = 0; nt < 4; nt++) {
            int col = bn + wn * 32 + nt * 8 + lc * 2;
            float2 bv = *(const float2*)(bias + col);
            #pragma unroll
            for (int half = 0; half < 2; half++) {
                size_t row = (size_t)(bm + wm * 64 + mt * 16 + lr + half * 8);
                float v0 = acc[mt][nt][half * 2 + 0] + bv.x;
                float v1 = acc[mt][nt][half * 2 + 1] + bv.y;
                if (EPI == EPI_BIAS_RES) {
                    float2 rv = *(const float2*)(R + row * N + col);
                    v0 += rv.x; v1 += rv.y;
                }
                if (EPI == EPI_BIAS_GELU) {
                    v0 = 0.5f * v0 * (1.f + erff(v0 * 0.7071067811865476f));
                    v1 = 0.5f * v1 * (1.f + erff(v1 * 0.7071067811865476f));
                }
                if (OUTH) {
                    *(__half2*)(Ch + row * N + col) = __floats2half2_rn(v0, v1);
                } else {
                    float2 o = {v0, v1};
                    *(float2*)(Cf + row * N + col) = o;
                }
            }
        }
    }
}

// ---------------- weight fp32 -> fp16 -------------------------------------------
__global__ void cvt_h4(const float4* __restrict__ in, __half2* __restrict__ out2, int n4) {
    int i = blockIdx.x * 256 + threadIdx.x;
    if (i < n4) {
        float4 v = in[i];
        out2[i * 2]     = __floats2half2_rn(v.x, v.y);
        out2[i * 2 + 1] = __floats2half2_rn(v.z, v.w);
    }
}

// ---------------- block reduction (256 threads) ----------------------------------
__device__ __forceinline__ float block_sum256(float v) {
    __shared__ float sh[8];
    int lane = threadIdx.x & 31, w = threadIdx.x >> 5;
    #pragma unroll
    for (int o = 16; o > 0; o >>= 1) v += __shfl_down_sync(0xffffffffu, v, o);
    if (lane == 0) sh[w] = v;
    __syncthreads();
    float r = 0.f;
    #pragma unroll
    for (int i = 0; i < 8; i++) r += sh[i];
    __syncthreads();
    return r;
}

// ---------------- LayerNorm (fp16 output) ----------------------------------------
__global__ void ln_kernel(const float* __restrict__ x, const float* __restrict__ w,
                          const float* __restrict__ bb, __half* __restrict__ y) {
    int row = blockIdx.x;
    const float* xr = x + (size_t)row * D_;
    int t = threadIdx.x;
    float v0 = xr[t], v1 = xr[t + 256], v2 = xr[t + 512];
    float s = block_sum256(v0 + v1 + v2);
    float mu = s * (1.f / 768.f);
    float d0 = v0 - mu, d1 = v1 - mu, d2 = v2 - mu;
    float vs = block_sum256(d0 * d0 + d1 * d1 + d2 * d2);
    float rstd = rsqrtf(vs * (1.f / 768.f) + 1e-5f);
    __half* yr = y + (size_t)row * D_;
    yr[t]       = __float2half(d0 * rstd * w[t]       + bb[t]);
    yr[t + 256] = __float2half(d1 * rstd * w[t + 256] + bb[t + 256]);
    yr[t + 512] = __float2half(d2 * rstd * w[t + 512] + bb[t + 512]);
}

// ---------------- Attention: fp16 tensor-core flash, windowed causal -------------
// q-tile 128 (8 warps x 16 rows), key-tile 64, HD=64. m16n8k16 fp16, fp32 accum.
// P stays in registers (S C-fragments map directly onto PV A-fragments).
#define TQ 128
#define QPH 72
#define KPH 72
#define VPH 72
#define ATTN_SMEM_BYTES ((128 * QPH + 64 * KPH + 64 * VPH) * 2 + 256)

__global__ void __launch_bounds__(256, 2) attn_h_kernel(
    const __half* __restrict__ qkv, const int* __restrict__ amask,
    __half* __restrict__ out)
{
    extern __shared__ char dynsm[];
    __half* Qs = (__half*)dynsm;         // [128][QPH]
    __half* Kn = Qs + 128 * QPH;         // [64][KPH]
    __half* Vs = Kn + 64 * KPH;          // [64][VPH]
    int* kmsk = (int*)(Vs + 64 * VPH);

    const int qi = blockIdx.x, h = blockIdx.y, b = blockIdx.z;
    const int qb = qi * TQ;
    const int tid = threadIdx.x, wid = tid >> 5, lane = tid & 31;
    const int lr = lane >> 2, lc = lane & 3;
    const int wq = wid * 16;
    const int sel = lane >> 3;
    const int vrow = (sel & 1) * 8 + (lane & 7);
    const int vcol = (sel >> 1) * 8;

    // stage Q (fp16), pull scaled fragments
    {
        int r = tid >> 1, cb = (tid & 1) * 32;
        const __half* src = qkv + (size_t)(b * T_ + qb + r) * (3 * D_) + h * 64 + cb;
        #pragma unroll
        for (int c = 0; c < 4; c++)
            *(uint4*)(Qs + r * QPH + cb + c * 8) = *(const uint4*)(src + c * 8);
    }
    __syncthreads();
    const __half2 sc2 = __floats2half2_rn(0.125f, 0.125f);
    uint32_t qa[4][4];
    #pragma unroll
    for (int kk = 0; kk < 4; kk++) {
        const __half* p = Qs + (size_t)(wq + lr) * QPH + kk * 16 + lc * 2;
        qa[kk][0] = h2u(__hmul2(*(const __half2*)p, sc2));
        qa[kk][1] = h2u(__hmul2(*(const __half2*)(p + 8 * QPH), sc2));
        qa[kk][2] = h2u(__hmul2(*(const __half2*)(p + 8), sc2));
        qa[kk][3] = h2u(__hmul2(*(const __half2*)(p + 8 * QPH + 8), sc2));
    }

    float o[8][4];
    #pragma unroll
    for (int j = 0; j < 8; j++)
        #pragma unroll
        for (int k = 0; k < 4; k++) o[j][k] = 0.f;
    float mrow[2] = {-1e30f, -1e30f}, lrow[2] = {0.f, 0.f};

    int lo = qb - (WIN_ - 1);
    const int kt0 = (lo > 0 ? lo : 0) >> 6;
    const int kt1 = (qb + TQ - 1) >> 6;

    for (int kt = kt0; kt <= kt1; kt++) {
        const int kb = kt * 64;
        __syncthreads();
        {
            int r = tid >> 2, cb = (tid & 3) * 16;
            const __half* kp = qkv + (size_t)(b * T_ + kb + r) * (3 * D_) + D_ + h * 64 + cb;
            *(uint4*)(Kn + r * KPH + cb)     = *(const uint4*)kp;
            *(uint4*)(Kn + r * KPH + cb + 8) = *(const uint4*)(kp + 8);
            *(uint4*)(Vs + r * VPH + cb)     = *(const uint4*)(kp + D_);
            *(uint4*)(Vs + r * VPH + cb + 8) = *(const uint4*)(kp + D_ + 8);
            if (tid < 64) kmsk[tid] = amask[b * T_ + kb + tid];
        }
        __syncthreads();

        // S = (Q*scale) K^T   (per warp: 16 x 64)
        float s[8][4];
        #pragma unroll
        for (int j = 0; j < 8; j++) {
            s[j][0] = s[j][1] = s[j][2] = s[j][3] = 0.f;
            #pragma unroll
            for (int kk = 0; kk < 4; kk++) {
                const __half* p = Kn + (size_t)(j * 8 + lr) * KPH + kk * 16 + lc * 2;
                uint32_t bf[2] = {*(const uint32_t*)p, *(const uint32_t*)(p + 8)};
                mma1616(s[j], qa[kk], bf);
            }
        }

        // mask
        #pragma unroll
        for (int j = 0; j < 8; j++) {
            int kg0 = kb + j * 8 + lc * 2, kg1 = kg0 + 1;
            int km0 = kmsk[j * 8 + lc * 2], km1 = kmsk[j * 8 + lc * 2 + 1];
            #pragma unroll
            for (int half = 0; half < 2; half++) {
                int qg = qb + wq + lr + half * 8;
                bool v0 = (kg0 <= qg) && (kg0 > qg - WIN_) && (km0 != 0);
                bool v1 = (kg1 <= qg) && (kg1 > qg - WIN_) && (km1 != 0);
                if (!v0) s[j][half * 2 + 0] = -1e30f;
                if (!v1) s[j][half * 2 + 1] = -1e30f;
            }
        }

        // online softmax (quad reductions)
        float mnew[2], alpha[2], lsum[2];
        #pragma unroll
        for (int half = 0; half < 2; half++) {
            float m = -1e30f;
            #pragma unroll
            for (int j = 0; j < 8; j++)
                m = fmaxf(m, fmaxf(s[j][half * 2], s[j][half * 2 + 1]));
            m = fmaxf(m, __shfl_xor_sync(0xffffffffu, m, 1));
            m = fmaxf(m, __shfl_xor_sync(0xffffffffu, m, 2));
            mnew[half] = fmaxf(mrow[half], m);
            alpha[half] = __expf(mrow[half] - mnew[half]);
            lsum[half] = 0.f;
        }
        #pragma unroll
        for (int j = 0; j < 8; j++) {
            #pragma unroll
            for (int half = 0; half < 2; half++) {
                float s0 = s[j][half * 2], s1 = s[j][half * 2 + 1];
                float p0 = (s0 <= -1e29f) ? 0.f : __expf(s0 - mnew[half]);
                float p1 = (s1 <= -1e29f) ? 0.f : __expf(s1 - mnew[half]);
                s[j][half * 2] = p0; s[j][half * 2 + 1] = p1;
                lsum[half] += p0 + p1;
            }
        }
        #pragma unroll
        for (int half = 0; half < 2; half++) {
            lsum[half] += __shfl_xor_sync(0xffffffffu, lsum[half], 1);
            lsum[half] += __shfl_xor_sync(0xffffffffu, lsum[half], 2);
            lrow[half] = lrow[half] * alpha[half] + lsum[half];
            mrow[half] = mnew[half];
        }
        #pragma unroll
        for (int j = 0; j < 8; j++) {
            o[j][0] *= alpha[0]; o[j][1] *= alpha[0];
            o[j][2] *= alpha[1]; o[j][3] *= alpha[1];
        }

        // O += P V : P converted in registers, V via ldmatrix.trans
        const uint32_t vbase = smem_to_u32(Vs);
        #pragma unroll
        for (int kk = 0; kk < 4; kk++) {
            uint32_t pa[4] = {
                h2u(__floats2half2_rn(s[2 * kk][0],     s[2 * kk][1])),
                h2u(__floats2half2_rn(s[2 * kk][2],     s[2 * kk][3])),
                h2u(__floats2half2_rn(s[2 * kk + 1][0], s[2 * kk + 1][1])),
                h2u(__floats2half2_rn(s[2 * kk + 1][2], s[2 * kk + 1][3]))
            };
            #pragma unroll
            for (int jp = 0; jp < 4; jp++) {
                uint32_t vb[4];
                uint32_t addr = vbase + ((kk * 16 + vrow) * VPH + jp * 16 + vcol) * 2;
                LDSM4T(vb[0], vb[1], vb[2], vb[3], addr);
                mma1616(o[jp * 2],     pa, vb);
                mma1616(o[jp * 2 + 1], pa, vb + 2);
            }
        }
    }

    // normalize + write fp16
    float linv[2] = {1.f / lrow[0], 1.f / lrow[1]};
    #pragma unroll
    for (int half = 0; half < 2; half++) {
        size_t row = (size_t)(b * T_ + qb + wq + lr + half * 8);
        __half* op = out + row * D_ + h * 64;
        #pragma unroll
        for (int j = 0; j < 8; j++)
            *(__half2*)(op + j * 8 + lc * 2) =
                __floats2half2_rn(o[j][half * 2] * linv[half], o[j][half * 2 + 1] * linv[half]);
    }
}

// ---------------- launch -----------------------------------------------------------
extern "C" void kernel_launch(void* const* d_in, const int* in_sizes, int n_in,
                              void* d_out, int out_size)
{
    const float* x      = (const float*)d_in[0];
    const int*   amask  = (const int*)d_in[1];
    const float* ln1_w  = (const float*)d_in[2];
    const float* ln1_b  = (const float*)d_in[3];
    const float* w_attn = (const float*)d_in[4];
    const float* b_attn = (const float*)d_in[5];
    const float* w_proj = (const float*)d_in[6];
    const float* b_proj = (const float*)d_in[7];
    const float* ln2_w  = (const float*)d_in[8];
    const float* ln2_b  = (const float*)d_in[9];
    const float* w_fc   = (const float*)d_in[10];
    const float* b_fc   = (const float*)d_in[11];
    const float* w_fcp  = (const float*)d_in[12];
    const float* b_fcp  = (const float*)d_in[13];
    float* out = (float*)d_out;

    __half *p_x1h, *p_qkvh, *p_attnh, *p_hh, *p_wah, *p_wph, *p_wfh, *p_wfph;
    float* p_x2;
    cudaGetSymbolAddress((void**)&p_x1h,   g_x1h);
    cudaGetSymbolAddress((void**)&p_qkvh,  g_qkvh);
    cudaGetSymbolAddress((void**)&p_attnh, g_attnh);
    cudaGetSymbolAddress((void**)&p_x2,    g_x2);
    cudaGetSymbolAddress((void**)&p_hh,    g_hh);
    cudaGetSymbolAddress((void**)&p_wah,   g_wah);
    cudaGetSymbolAddress((void**)&p_wph,   g_wph);
    cudaGetSymbolAddress((void**)&p_wfh,   g_wfh);
    cudaGetSymbolAddress((void**)&p_wfph,  g_wfph);

    cudaFuncSetAttribute(hgemm<EPI_BIAS, true>,       cudaFuncAttributeMaxDynamicSharedMemorySize, GEMM_SMEM);
    cudaFuncSetAttribute(hgemm<EPI_BIAS_RES, false>,  cudaFuncAttributeMaxDynamicSharedMemorySize, GEMM_SMEM);
    cudaFuncSetAttribute(hgemm<EPI_BIAS_GELU, true>,  cudaFuncAttributeMaxDynamicSharedMemorySize, GEMM_SMEM);
    cudaFuncSetAttribute(attn_h_kernel, cudaFuncAttributeMaxDynamicSharedMemorySize, ATTN_SMEM_BYTES);

    // weights fp32 -> fp16 (once per launch)
    cvt_h4<<<(768 * 2304 / 4 + 255) / 256, 256>>>((const float4*)w_attn, (__half2*)p_wah, 768 * 2304 / 4);
    cvt_h4<<<(768 * 768 / 4 + 255) / 256, 256>>>((const float4*)w_proj, (__half2*)p_wph, 768 * 768 / 4);
    cvt_h4<<<(768 * 3072 / 4 + 255) / 256, 256>>>((const float4*)w_fc,  (__half2*)p_wfh, 768 * 3072 / 4);
    cvt_h4<<<(3072 * 768 / 4 + 255) / 256, 256>>>((const float4*)w_fcp, (__half2*)p_wfph, 3072 * 768 / 4);

    // 1) ln1 -> fp16
    ln_kernel<<<M_, 256>>>(x, ln1_w, ln1_b, p_x1h);
    // 2) qkv = x1 @ w_attn + b_attn   [8192 x 2304 x 768], fp16 out
    hgemm<EPI_BIAS, true><<<dim3(2304 / 128, M_ / 128), 256, GEMM_SMEM>>>(
        p_x1h, p_wah, b_attn, nullptr, nullptr, p_qkvh, 2304, 768);
    // 3) attention (fp16 tensor-core flash)
    attn_h_kernel<<<dim3(T_ / TQ, H_, B_), 256, ATTN_SMEM_BYTES>>>(p_qkvh, amask, p_attnh);
    // 4) x2 = attn @ w_proj + b_proj + x   [8192 x 768 x 768], fp32 out
    hgemm<EPI_BIAS_RES, false><<<dim3(768 / 128, M_ / 128), 256, GEMM_SMEM>>>(
        p_attnh, p_wph, b_proj, x, p_x2, nullptr, 768, 768);
    // 5) ln2 -> fp16
    ln_kernel<<<M_, 256>>>(p_x2, ln2_w, ln2_b, p_x1h);
    // 6) h = gelu(x1 @ w_fc + b_fc)   [8192 x 3072 x 768], fp16 out
    hgemm<EPI_BIAS_GELU, true><<<dim3(3072 / 128, M_ / 128), 256, GEMM_SMEM>>>(
        p_x1h, p_wfh, b_fc, nullptr, nullptr, p_hh, 3072, 768);
    // 7) out = h @ w_fc_proj + b_fc_proj + x2   [8192 x 768 x 3072], fp32 out
    hgemm<EPI_BIAS_RES, false><<<dim3(768 / 128, M_ / 128), 256, GEMM_SMEM>>>(
        p_hh, p_wfph, b_fcp, p_x2, out, nullptr, 768, 3072);
}

// round 6
// speedup vs baseline: 5.5461x; 1.1103x over previous
#include <cuda_runtime.h>
#include <cuda_fp16.h>
#include <math.h>
#include <stdint.h>

#define B_   8
#define T_   1024
#define D_   768
#define H_   12
#define WIN_ 768
#define M_   (B_*T_)   // 8192

// ---------------- scratch (static device globals) ---------------------------
__device__ __half g_x1h[M_ * D_];
__device__ __half g_qkvh[M_ * 3 * D_];
__device__ __half g_attnh[M_ * D_];
__device__ float  g_x2[M_ * D_];
__device__ __half g_hh[M_ * 4 * D_];
__device__ __half g_wah[D_ * 3 * D_];
__device__ __half g_wph[D_ * D_];
__device__ __half g_wfh[D_ * 4 * D_];
__device__ __half g_wfph[4 * D_ * D_];

// ---------------- helpers -----------------------------------------------------
__device__ __forceinline__ uint32_t smem_to_u32(const void* p) {
    uint32_t a;
    asm("{ .reg .u64 t; cvta.to.shared.u64 t, %1; cvt.u32.u64 %0, t; }" : "=r"(a) : "l"(p));
    return a;
}
__device__ __forceinline__ uint32_t h2u(__half2 v) { return *(uint32_t*)&v; }

#define CP16(saddr, gptr) \
    asm volatile("cp.async.cg.shared.global [%0], [%1], 16;" :: "r"(saddr), "l"(gptr))
#define CP_COMMIT() asm volatile("cp.async.commit_group;" ::: "memory")
#define CP_WAIT1()  asm volatile("cp.async.wait_group 1;" ::: "memory")

#define LDSM4(r0, r1, r2, r3, addr) \
    asm volatile("ldmatrix.sync.aligned.m8n8.x4.shared.b16 {%0,%1,%2,%3}, [%4];" \
        : "=r"(r0), "=r"(r1), "=r"(r2), "=r"(r3) : "r"(addr))
#define LDSM4T(r0, r1, r2, r3, addr) \
    asm volatile("ldmatrix.sync.aligned.m8n8.x4.trans.shared.b16 {%0,%1,%2,%3}, [%4];" \
        : "=r"(r0), "=r"(r1), "=r"(r2), "=r"(r3) : "r"(addr))

__device__ __forceinline__ void mma1616(float* d, const uint32_t* a, const uint32_t* b) {
    asm volatile(
        "mma.sync.aligned.m16n8k16.row.col.f32.f16.f16.f32 "
        "{%0,%1,%2,%3}, {%4,%5,%6,%7}, {%8,%9}, {%0,%1,%2,%3};"
        : "+f"(d[0]), "+f"(d[1]), "+f"(d[2]), "+f"(d[3])
        : "r"(a[0]), "r"(a[1]), "r"(a[2]), "r"(a[3]), "r"(b[0]), "r"(b[1]));
}

// ---------------- fp16 tensor-core GEMM ----------------------------------------
// C[M,N] = A[M,K] @ W[K,N] + bias (+res / gelu). A, W fp16; accum fp32.
// 128x128 tile, BK=32, 8 warps (64x32 each), 3-stage cp.async pipeline,
// single __syncthreads per K-iter, all fragments via ldmatrix.
enum { EPI_BIAS = 0, EPI_BIAS_RES = 1, EPI_BIAS_GELU = 2 };

#define APADH 40                       // A tile row stride (halves)
#define BPADH 136                      // B tile row stride (halves)
#define A_ST (128 * APADH)
#define B_ST (32 * BPADH)
#define STG_H (A_ST + B_ST)
#define GEMM_SMEM (3 * STG_H * 2)      // 56832 bytes

template <int EPI, bool OUTH>
__global__ void __launch_bounds__(256, 2) hgemm(
    const __half* __restrict__ A, const __half* __restrict__ W,
    const float* __restrict__ bias, const float* __restrict__ R,
    float* __restrict__ Cf, __half* __restrict__ Ch, int N, int K)
{
    extern __shared__ char dynsm[];
    __half* smh = (__half*)dynsm;
    const int tid = threadIdx.x;
    const int wid = tid >> 5, lane = tid & 31;
    const int wm = wid >> 2, wn = wid & 3;
    const int bm = blockIdx.y << 7, bn = blockIdx.x << 7;
    const int lr = lane >> 2, lc = lane & 3;
    // ldmatrix addressing
    const int arow = lane & 15, acol8 = (lane >> 4) * 8;           // A (non-trans)
    const int sel = lane >> 3;
    const int brow = (sel & 1) * 8 + (lane & 7), bcol = (sel >> 1) * 8;  // B (trans)
    const int NIT = K >> 5;

    const int am = tid >> 1, ac = tid & 1;
    const int br = tid >> 4, bc = tid & 15;
    const __half* gA = A + (size_t)(bm + am) * K;
    const __half* gB = W + (size_t)br * N + bn;

    float acc[4][4][4];
    #pragma unroll
    for (int i = 0; i < 4; i++)
        #pragma unroll
        for (int j = 0; j < 4; j++)
            #pragma unroll
            for (int k = 0; k < 4; k++) acc[i][j][k] = 0.f;

    auto load_stage = [&](int s, int kt) {
        __half* Ah = smh + s * STG_H;
        __half* Bh = Ah + A_ST;
        uint32_t sa = smem_to_u32(Ah + am * APADH + ac * 16);
        const __half* ga = gA + (kt << 5) + ac * 16;
        CP16(sa, ga);
        CP16(sa + 16, ga + 8);
        uint32_t sb = smem_to_u32(Bh + br * BPADH + bc * 8);
        const __half* gb = gB + (size_t)(kt << 5) * N + bc * 8;
        CP16(sb, gb);
        CP16(sb + 16 * BPADH * 2, gb + (size_t)16 * N);
    };

    load_stage(0, 0); CP_COMMIT();
    load_stage(1, 1); CP_COMMIT();

    for (int it = 0; it < NIT; it++) {
        CP_WAIT1();
        __syncthreads();
        if (it + 2 < NIT) load_stage((it + 2) % 3, it + 2);
        CP_COMMIT();

        const __half* Ah = smh + (it % 3) * STG_H;
        const __half* Bh = Ah + A_ST;
        const uint32_t abase = smem_to_u32(Ah);
        const uint32_t bbase = smem_to_u32(Bh);
        #pragma unroll
        for (int kk = 0; kk < 2; kk++) {
            uint32_t bfr[4][2];
            #pragma unroll
            for (int ntp = 0; ntp < 2; ntp++) {
                uint32_t addr = bbase +
                    ((kk * 16 + brow) * BPADH + wn * 32 + ntp * 16 + bcol) * 2;
                LDSM4T(bfr[ntp * 2][0], bfr[ntp * 2][1],
                       bfr[ntp * 2 + 1][0], bfr[ntp * 2 + 1][1], addr);
            }
            #pragma unroll
            for (int mt = 0; mt < 4; mt++) {
                uint32_t af[4];
                uint32_t aaddr = abase +
                    ((wm * 64 + mt * 16 + arow) * APADH + kk * 16 + acol8) * 2;
                LDSM4(af[0], af[1], af[2], af[3], aaddr);
                #pragma unroll
                for (int nt = 0; nt < 4; nt++)
                    mma1616(acc[mt][nt], af, bfr[nt]);
            }
        }
    }

    // epilogue
    #pragma unroll
    for (int mt = 0; mt < 4; mt++) {
        #pragma unroll
        for (int nt = 0; nt < 4; nt++) {
            int col = bn + wn * 32 + nt * 8 + lc * 2;
            float2 bv = *(const float2*)(bias + col);
            #pragma unroll
            for (int half = 0; half < 2; half++) {
                size_t row = (size_t)(bm + wm * 64 + mt * 16 + lr + half * 8);
                float v0 = acc[mt][nt][half * 2 + 0] + bv.x;
                float v1 = acc[mt][nt][half * 2 + 1] + bv.y;
                if (EPI == EPI_BIAS_RES) {
                    float2 rv = *(const float2*)(R + row * N + col);
                    v0 += rv.x; v1 += rv.y;
                }
                if (EPI == EPI_BIAS_GELU) {
                    v0 = 0.5f * v0 * (1.f + erff(v0 * 0.7071067811865476f));
                    v1 = 0.5f * v1 * (1.f + erff(v1 * 0.7071067811865476f));
                }
                if (OUTH) {
                    *(__half2*)(Ch + row * N + col) = __floats2half2_rn(v0, v1);
                } else {
                    float2 o = {v0, v1};
                    *(float2*)(Cf + row * N + col) = o;
                }
            }
        }
    }
}

// ---------------- weight fp32 -> fp16 -------------------------------------------
__global__ void cvt_h4(const float4* __restrict__ in, __half2* __restrict__ out2, int n4) {
    int i = blockIdx.x * 256 + threadIdx.x;
    if (i < n4) {
        float4 v = in[i];
        out2[i * 2]     = __floats2half2_rn(v.x, v.y);
        out2[i * 2 + 1] = __floats2half2_rn(v.z, v.w);
    }
}

// ---------------- block reduction (256 threads) ----------------------------------
__device__ __forceinline__ float block_sum256(float v) {
    __shared__ float sh[8];
    int lane = threadIdx.x & 31, w = threadIdx.x >> 5;
    #pragma unroll
    for (int o = 16; o > 0; o >>= 1) v += __shfl_down_sync(0xffffffffu, v, o);
    if (lane == 0) sh[w] = v;
    __syncthreads();
    float r = 0.f;
    #pragma unroll
    for (int i = 0; i < 8; i++) r += sh[i];
    __syncthreads();
    return r;
}

// ---------------- LayerNorm (fp16 output) ----------------------------------------
__global__ void ln_kernel(const float* __restrict__ x, const float* __restrict__ w,
                          const float* __restrict__ bb, __half* __restrict__ y) {
    int row = blockIdx.x;
    const float* xr = x + (size_t)row * D_;
    int t = threadIdx.x;
    float v0 = xr[t], v1 = xr[t + 256], v2 = xr[t + 512];
    float s = block_sum256(v0 + v1 + v2);
    float mu = s * (1.f / 768.f);
    float d0 = v0 - mu, d1 = v1 - mu, d2 = v2 - mu;
    float vs = block_sum256(d0 * d0 + d1 * d1 + d2 * d2);
    float rstd = rsqrtf(vs * (1.f / 768.f) + 1e-5f);
    __half* yr = y + (size_t)row * D_;
    yr[t]       = __float2half(d0 * rstd * w[t]       + bb[t]);
    yr[t + 256] = __float2half(d1 * rstd * w[t + 256] + bb[t + 256]);
    yr[t + 512] = __float2half(d2 * rstd * w[t + 512] + bb[t + 512]);
}

// ---------------- Attention: fp16 tensor-core flash, windowed causal -------------
// q-tile 128 (8 warps x 16 rows), key-tile 64, HD=64. m16n8k16 fp16, fp32 accum.
// K fragments via ldmatrix.x4 (B-frag == A-frag of transposed storage); P in regs.
#define TQ 128
#define QPH 72
#define KPH 72
#define VPH 72
#define ATTN_SMEM_BYTES ((128 * QPH + 64 * KPH + 64 * VPH) * 2 + 256)

__global__ void __launch_bounds__(256, 2) attn_h_kernel(
    const __half* __restrict__ qkv, const int* __restrict__ amask,
    __half* __restrict__ out)
{
    extern __shared__ char dynsm[];
    __half* Qs = (__half*)dynsm;         // [128][QPH]
    __half* Kn = Qs + 128 * QPH;         // [64][KPH]  key-major K
    __half* Vs = Kn + 64 * KPH;          // [64][VPH]  key-major V
    int* kmsk = (int*)(Vs + 64 * VPH);

    const int qi = blockIdx.x, h = blockIdx.y, b = blockIdx.z;
    const int qb = qi * TQ;
    const int tid = threadIdx.x, wid = tid >> 5, lane = tid & 31;
    const int lr = lane >> 2, lc = lane & 3;
    const int wq = wid * 16;
    const int sel = lane >> 3;
    const int vrow = (sel & 1) * 8 + (lane & 7);
    const int vcol = (sel >> 1) * 8;
    // K ldmatrix: row within 16-key pair block, 8-col selector
    const int krow = (lane & 7) + ((lane >> 4) << 3);
    const int kcol = ((lane >> 3) & 1) * 8;

    // stage Q (fp16), pull scaled fragments
    {
        int r = tid >> 1, cb = (tid & 1) * 32;
        const __half* src = qkv + (size_t)(b * T_ + qb + r) * (3 * D_) + h * 64 + cb;
        #pragma unroll
        for (int c = 0; c < 4; c++)
            *(uint4*)(Qs + r * QPH + cb + c * 8) = *(const uint4*)(src + c * 8);
    }
    __syncthreads();
    const __half2 sc2 = __floats2half2_rn(0.125f, 0.125f);
    uint32_t qa[4][4];
    #pragma unroll
    for (int kk = 0; kk < 4; kk++) {
        const __half* p = Qs + (size_t)(wq + lr) * QPH + kk * 16 + lc * 2;
        qa[kk][0] = h2u(__hmul2(*(const __half2*)p, sc2));
        qa[kk][1] = h2u(__hmul2(*(const __half2*)(p + 8 * QPH), sc2));
        qa[kk][2] = h2u(__hmul2(*(const __half2*)(p + 8), sc2));
        qa[kk][3] = h2u(__hmul2(*(const __half2*)(p + 8 * QPH + 8), sc2));
    }

    float o[8][4];
    #pragma unroll
    for (int j = 0; j < 8; j++)
        #pragma unroll
        for (int k = 0; k < 4; k++) o[j][k] = 0.f;
    float mrow[2] = {-1e30f, -1e30f}, lrow[2] = {0.f, 0.f};

    int lo = qb - (WIN_ - 1);
    const int kt0 = (lo > 0 ? lo : 0) >> 6;
    const int kt1 = (qb + TQ - 1) >> 6;

    for (int kt = kt0; kt <= kt1; kt++) {
        const int kb = kt * 64;
        __syncthreads();
        {
            int r = tid >> 2, cb = (tid & 3) * 16;
            const __half* kp = qkv + (size_t)(b * T_ + kb + r) * (3 * D_) + D_ + h * 64 + cb;
            *(uint4*)(Kn + r * KPH + cb)     = *(const uint4*)kp;
            *(uint4*)(Kn + r * KPH + cb + 8) = *(const uint4*)(kp + 8);
            *(uint4*)(Vs + r * VPH + cb)     = *(const uint4*)(kp + D_);
            *(uint4*)(Vs + r * VPH + cb + 8) = *(const uint4*)(kp + D_ + 8);
            if (tid < 64) kmsk[tid] = amask[b * T_ + kb + tid];
        }
        __syncthreads();

        // S = (Q*scale) K^T   (per warp: 16 x 64); K frags via ldmatrix.x4
        float s[8][4];
        #pragma unroll
        for (int j = 0; j < 8; j++)
            s[j][0] = s[j][1] = s[j][2] = s[j][3] = 0.f;
        const uint32_t kbase = smem_to_u32(Kn);
        #pragma unroll
        for (int jp = 0; jp < 4; jp++) {
            #pragma unroll
            for (int kk = 0; kk < 4; kk++) {
                uint32_t kb4[4];
                uint32_t addr = kbase + ((jp * 16 + krow) * KPH + kk * 16 + kcol) * 2;
                LDSM4(kb4[0], kb4[1], kb4[2], kb4[3], addr);
                mma1616(s[jp * 2],     qa[kk], kb4);
                mma1616(s[jp * 2 + 1], qa[kk], kb4 + 2);
            }
        }

        // mask
        #pragma unroll
        for (int j = 0; j < 8; j++) {
            int kg0 = kb + j * 8 + lc * 2, kg1 = kg0 + 1;
            int km0 = kmsk[j * 8 + lc * 2], km1 = kmsk[j * 8 + lc * 2 + 1];
            #pragma unroll
            for (int half = 0; half < 2; half++) {
                int qg = qb + wq + lr + half * 8;
                bool v0 = (kg0 <= qg) && (kg0 > qg - WIN_) && (km0 != 0);
                bool v1 = (kg1 <= qg) && (kg1 > qg - WIN_) && (km1 != 0);
                if (!v0) s[j][half * 2 + 0] = -1e30f;
                if (!v1) s[j][half * 2 + 1] = -1e30f;
            }
        }

        // online softmax (quad reductions)
        float mnew[2], alpha[2], lsum[2];
        #pragma unroll
        for (int half = 0; half < 2; half++) {
            float m = -1e30f;
            #pragma unroll
            for (int j = 0; j < 8; j++)
                m = fmaxf(m, fmaxf(s[j][half * 2], s[j][half * 2 + 1]));
            m = fmaxf(m, __shfl_xor_sync(0xffffffffu, m, 1));
            m = fmaxf(m, __shfl_xor_sync(0xffffffffu, m, 2));
            mnew[half] = fmaxf(mrow[half], m);
            alpha[half] = __expf(mrow[half] - mnew[half]);
            lsum[half] = 0.f;
        }
        #pragma unroll
        for (int j = 0; j < 8; j++) {
            #pragma unroll
            for (int half = 0; half < 2; half++) {
                float s0 = s[j][half * 2], s1 = s[j][half * 2 + 1];
                float p0 = (s0 <= -1e29f) ? 0.f : __expf(s0 - mnew[half]);
                float p1 = (s1 <= -1e29f) ? 0.f : __expf(s1 - mnew[half]);
                s[j][half * 2] = p0; s[j][half * 2 + 1] = p1;
                lsum[half] += p0 + p1;
            }
        }
        #pragma unroll
        for (int half = 0; half < 2; half++) {
            lsum[half] += __shfl_xor_sync(0xffffffffu, lsum[half], 1);
            lsum[half] += __shfl_xor_sync(0xffffffffu, lsum[half], 2);
            lrow[half] = lrow[half] * alpha[half] + lsum[half];
            mrow[half] = mnew[half];
        }
        #pragma unroll
        for (int j = 0; j < 8; j++) {
            o[j][0] *= alpha[0]; o[j][1] *= alpha[0];
            o[j][2] *= alpha[1]; o[j][3] *= alpha[1];
        }

        // O += P V : P converted in registers, V via ldmatrix.trans
        const uint32_t vbase = smem_to_u32(Vs);
        #pragma unroll
        for (int kk = 0; kk < 4; kk++) {
            uint32_t pa[4] = {
                h2u(__floats2half2_rn(s[2 * kk][0],     s[2 * kk][1])),
                h2u(__floats2half2_rn(s[2 * kk][2],     s[2 * kk][3])),
                h2u(__floats2half2_rn(s[2 * kk + 1][0], s[2 * kk + 1][1])),
                h2u(__floats2half2_rn(s[2 * kk + 1][2], s[2 * kk + 1][3]))
            };
            #pragma unroll
            for (int jp = 0; jp < 4; jp++) {
                uint32_t vb[4];
                uint32_t addr = vbase + ((kk * 16 + vrow) * VPH + jp * 16 + vcol) * 2;
                LDSM4T(vb[0], vb[1], vb[2], vb[3], addr);
                mma1616(o[jp * 2],     pa, vb);
                mma1616(o[jp * 2 + 1], pa, vb + 2);
            }
        }
    }

    // normalize + write fp16
    float linv[2] = {1.f / lrow[0], 1.f / lrow[1]};
    #pragma unroll
    for (int half = 0; half < 2; half++) {
        size_t row = (size_t)(b * T_ + qb + wq + lr + half * 8);
        __half* op = out + row * D_ + h * 64;
        #pragma unroll
        for (int j = 0; j < 8; j++)
            *(__half2*)(op + j * 8 + lc * 2) =
                __floats2half2_rn(o[j][half * 2] * linv[half], o[j][half * 2 + 1] * linv[half]);
    }
}

// ---------------- launch -----------------------------------------------------------
extern "C" void kernel_launch(void* const* d_in, const int* in_sizes, int n_in,
                              void* d_out, int out_size)
{
    const float* x      = (const float*)d_in[0];
    const int*   amask  = (const int*)d_in[1];
    const float* ln1_w  = (const float*)d_in[2];
    const float* ln1_b  = (const float*)d_in[3];
    const float* w_attn = (const float*)d_in[4];
    const float* b_attn = (const float*)d_in[5];
    const float* w_proj = (const float*)d_in[6];
    const float* b_proj = (const float*)d_in[7];
    const float* ln2_w  = (const float*)d_in[8];
    const float* ln2_b  = (const float*)d_in[9];
    const float* w_fc   = (const float*)d_in[10];
    const float* b_fc   = (const float*)d_in[11];
    const float* w_fcp  = (const float*)d_in[12];
    const float* b_fcp  = (const float*)d_in[13];
    float* out = (float*)d_out;

    __half *p_x1h, *p_qkvh, *p_attnh, *p_hh, *p_wah, *p_wph, *p_wfh, *p_wfph;
    float* p_x2;
    cudaGetSymbolAddress((void**)&p_x1h,   g_x1h);
    cudaGetSymbolAddress((void**)&p_qkvh,  g_qkvh);
    cudaGetSymbolAddress((void**)&p_attnh, g_attnh);
    cudaGetSymbolAddress((void**)&p_x2,    g_x2);
    cudaGetSymbolAddress((void**)&p_hh,    g_hh);
    cudaGetSymbolAddress((void**)&p_wah,   g_wah);
    cudaGetSymbolAddress((void**)&p_wph,   g_wph);
    cudaGetSymbolAddress((void**)&p_wfh,   g_wfh);
    cudaGetSymbolAddress((void**)&p_wfph,  g_wfph);

    cudaFuncSetAttribute(hgemm<EPI_BIAS, true>,       cudaFuncAttributeMaxDynamicSharedMemorySize, GEMM_SMEM);
    cudaFuncSetAttribute(hgemm<EPI_BIAS_RES, false>,  cudaFuncAttributeMaxDynamicSharedMemorySize, GEMM_SMEM);
    cudaFuncSetAttribute(hgemm<EPI_BIAS_GELU, true>,  cudaFuncAttributeMaxDynamicSharedMemorySize, GEMM_SMEM);
    cudaFuncSetAttribute(attn_h_kernel, cudaFuncAttributeMaxDynamicSharedMemorySize, ATTN_SMEM_BYTES);

    // weights fp32 -> fp16 (once per launch)
    cvt_h4<<<(768 * 2304 / 4 + 255) / 256, 256>>>((const float4*)w_attn, (__half2*)p_wah, 768 * 2304 / 4);
    cvt_h4<<<(768 * 768 / 4 + 255) / 256, 256>>>((const float4*)w_proj, (__half2*)p_wph, 768 * 768 / 4);
    cvt_h4<<<(768 * 3072 / 4 + 255) / 256, 256>>>((const float4*)w_fc,  (__half2*)p_wfh, 768 * 3072 / 4);
    cvt_h4<<<(3072 * 768 / 4 + 255) / 256, 256>>>((const float4*)w_fcp, (__half2*)p_wfph, 3072 * 768 / 4);

    // 1) ln1 -> fp16
    ln_kernel<<<M_, 256>>>(x, ln1_w, ln1_b, p_x1h);
    // 2) qkv = x1 @ w_attn + b_attn   [8192 x 2304 x 768], fp16 out
    hgemm<EPI_BIAS, true><<<dim3(2304 / 128, M_ / 128), 256, GEMM_SMEM>>>(
        p_x1h, p_wah, b_attn, nullptr, nullptr, p_qkvh, 2304, 768);
    // 3) attention (fp16 tensor-core flash)
    attn_h_kernel<<<dim3(T_ / TQ, H_, B_), 256, ATTN_SMEM_BYTES>>>(p_qkvh, amask, p_attnh);
    // 4) x2 = attn @ w_proj + b_proj + x   [8192 x 768 x 768], fp32 out
    hgemm<EPI_BIAS_RES, false><<<dim3(768 / 128, M_ / 128), 256, GEMM_SMEM>>>(
        p_attnh, p_wph, b_proj, x, p_x2, nullptr, 768, 768);
    // 5) ln2 -> fp16
    ln_kernel<<<M_, 256>>>(p_x2, ln2_w, ln2_b, p_x1h);
    // 6) h = gelu(x1 @ w_fc + b_fc)   [8192 x 3072 x 768], fp16 out
    hgemm<EPI_BIAS_GELU, true><<<dim3(3072 / 128, M_ / 128), 256, GEMM_SMEM>>>(
        p_x1h, p_wfh, b_fc, nullptr, nullptr, p_hh, 3072, 768);
    // 7) out = h @ w_fc_proj + b_fc_proj + x2   [8192 x 768 x 3072], fp32 out
    hgemm<EPI_BIAS_RES, false><<<dim3(768 / 128, M_ / 128), 256, GEMM_SMEM>>>(
        p_hh, p_wfph, b_fcp, p_x2, out, nullptr, 768, 3072);
}